// round 5
// baseline (speedup 1.0000x reference)
#include <cuda_runtime.h>

#define N_NODES 50000
#define N_EDGES 1600000
#define HID 256
#define SCAN_B 196   // ceil(N_NODES/256)

// ---------------- device scratch (static, no allocs) ----------------
__device__ float4 g_hb [N_NODES*HID/4];   // h buffer A
__device__ float4 g_hnb[N_NODES*HID/4];   // h buffer B
__device__ float4 g_agb[N_NODES*HID/4];   // (h_self + aggr) buffer / layer1 aggr
__device__ int    g_src[N_EDGES];
__device__ int    g_dst[N_EDGES];
__device__ int    g_deg[N_NODES];
__device__ int    g_rowptr[N_NODES + 1];
__device__ int    g_cur[N_NODES];
__device__ int    g_csrs[N_EDGES];        // src node, grouped by dst
__device__ float4 g_eas[N_EDGES * 2];     // edge attrs (7 + pad) in CSR order
__device__ int    g_bsum[SCAN_B];
__device__ int    g_boff[SCAN_B];
__device__ int    g_flag;                 // 1 = edge_index int64, 0 = int32

__device__ __forceinline__ void red_add_v2(float* a, float x, float y) {
    asm volatile("red.global.add.v2.f32 [%0], {%1,%2};"
                 :: "l"(a), "f"(x), "f"(y) : "memory");
}
__device__ __forceinline__ unsigned to_tf32(float v) {
    unsigned r;
    asm("cvt.rna.tf32.f32 %0, %1;" : "=r"(r) : "f"(v));
    return r;
}

// ---------------- dtype detection + index conversion ----------------
__global__ void k_detect(const void* ei) {
    if (threadIdx.x == 0) {
        const long long* p = (const long long*)ei;
        int is64 = 1;
        for (int i = 0; i < 64; i++) {
            long long v = p[i];
            if (v < 0 || v >= N_NODES) { is64 = 0; break; }
        }
        g_flag = is64;
    }
}

__global__ void k_convert(const void* ei) {
    int i = blockIdx.x * blockDim.x + threadIdx.x;
    if (i >= N_EDGES) return;
    if (g_flag) {
        const long long* p = (const long long*)ei;
        g_src[i] = (int)p[i];
        g_dst[i] = (int)p[N_EDGES + i];
    } else {
        const int* p = (const int*)ei;
        g_src[i] = p[i];
        g_dst[i] = p[N_EDGES + i];
    }
}

// ---------------- CSR build ----------------
__global__ void k_hist() {
    int i = blockIdx.x * blockDim.x + threadIdx.x;
    if (i < N_EDGES) atomicAdd(&g_deg[g_dst[i]], 1);
}

__global__ void k_part() {
    __shared__ int sm[256];
    int t = threadIdx.x;
    int n = blockIdx.x * 256 + t;
    int v = (n < N_NODES) ? g_deg[n] : 0;
    sm[t] = v;
    __syncthreads();
    for (int o = 128; o; o >>= 1) {
        if (t < o) sm[t] += sm[t + o];
        __syncthreads();
    }
    if (t == 0) g_bsum[blockIdx.x] = sm[0];
}

__global__ void k_scanb() {
    __shared__ int sm[256];
    int t = threadIdx.x;
    int v = (t < SCAN_B) ? g_bsum[t] : 0;
    sm[t] = v;
    __syncthreads();
    for (int o = 1; o < 256; o <<= 1) {
        int u = (t >= o) ? sm[t - o] : 0;
        __syncthreads();
        sm[t] += u;
        __syncthreads();
    }
    if (t < SCAN_B) g_boff[t] = sm[t] - v;   // exclusive
    if (t == 0) g_rowptr[N_NODES] = N_EDGES;
}

__global__ void k_rowptr() {
    __shared__ int sm[256];
    int t = threadIdx.x;
    int n = blockIdx.x * 256 + t;
    int v = (n < N_NODES) ? g_deg[n] : 0;
    sm[t] = v;
    __syncthreads();
    for (int o = 1; o < 256; o <<= 1) {
        int u = (t >= o) ? sm[t - o] : 0;
        __syncthreads();
        sm[t] += u;
        __syncthreads();
    }
    if (n < N_NODES) {
        int r = g_boff[blockIdx.x] + sm[t] - v;
        g_rowptr[n] = r;
        g_cur[n] = r;
    }
}

__global__ void k_fill(const float* __restrict__ ea) {
    int e = blockIdx.x * blockDim.x + threadIdx.x;
    if (e >= N_EDGES) return;
    int d = g_dst[e];
    int pos = atomicAdd(&g_cur[d], 1);
    g_csrs[pos] = g_src[e];
    const float* a = ea + (size_t)e * 7;
    float4 v0 = make_float4(a[0], a[1], a[2], a[3]);
    float4 v1 = make_float4(a[4], a[5], a[6], 0.f);
    g_eas[pos * 2 + 0] = v0;
    g_eas[pos * 2 + 1] = v1;
}

// ---------------- layer 1 scatter (C = 2, atomic push) ----------------
__global__ void k_scatter1(const float* __restrict__ x,
                           const float* __restrict__ ea,
                           const float* __restrict__ We1,
                           const float* __restrict__ be1) {
    int e = blockIdx.x * blockDim.x + threadIdx.x;
    if (e >= N_EDGES) return;
    float a[7];
#pragma unroll
    for (int k = 0; k < 7; k++) a[k] = ea[e * 7 + k];
    float e0 = __ldg(&be1[0]), e1 = __ldg(&be1[1]);
#pragma unroll
    for (int k = 0; k < 7; k++) {
        e0 += a[k] * __ldg(&We1[k * 2 + 0]);
        e1 += a[k] * __ldg(&We1[k * 2 + 1]);
    }
    int s = g_src[e], d = g_dst[e];
    float m0 = fmaxf(x[2 * s + 0] + e0, 0.f);
    float m1 = fmaxf(x[2 * s + 1] + e1, 0.f);
    red_add_v2(((float*)g_agb) + 2 * d, m0, m1);
}

// ---------------- layer 1 nn ----------------
__global__ void k_layer1nn(const float* __restrict__ x,
                           const float* __restrict__ W1,
                           const float* __restrict__ b1) {
    int n = blockIdx.x;
    int c = threadIdx.x;
    const float* ag = (const float*)g_agb;
    float a0 = x[2 * n + 0] + ag[2 * n + 0];
    float a1 = x[2 * n + 1] + ag[2 * n + 1];
    float v = b1[c] + a0 * W1[c] + a1 * W1[HID + c];
    ((float*)g_hb)[n * HID + c] = fmaxf(v, 0.f);
}

// ---------------- layers 2/3 aggregation: CSR pull ----------------
__device__ __forceinline__ void aggr_step(
    float4& acc, const float4* w, float4 bb,
    float4 a0, float4 a1, float4 h)
{
    float4 m = bb;
    m.x += a0.x * w[0].x; m.y += a0.x * w[0].y; m.z += a0.x * w[0].z; m.w += a0.x * w[0].w;
    m.x += a0.y * w[1].x; m.y += a0.y * w[1].y; m.z += a0.y * w[1].z; m.w += a0.y * w[1].w;
    m.x += a0.z * w[2].x; m.y += a0.z * w[2].y; m.z += a0.z * w[2].z; m.w += a0.z * w[2].w;
    m.x += a0.w * w[3].x; m.y += a0.w * w[3].y; m.z += a0.w * w[3].z; m.w += a0.w * w[3].w;
    m.x += a1.x * w[4].x; m.y += a1.x * w[4].y; m.z += a1.x * w[4].z; m.w += a1.x * w[4].w;
    m.x += a1.y * w[5].x; m.y += a1.y * w[5].y; m.z += a1.y * w[5].z; m.w += a1.y * w[5].w;
    m.x += a1.z * w[6].x; m.y += a1.z * w[6].y; m.z += a1.z * w[6].z; m.w += a1.z * w[6].w;
    acc.x += fmaxf(m.x + h.x, 0.f);
    acc.y += fmaxf(m.y + h.y, 0.f);
    acc.z += fmaxf(m.z + h.z, 0.f);
    acc.w += fmaxf(m.w + h.w, 0.f);
}

__global__ void __launch_bounds__(256)
k_aggr(int useHn, const float* __restrict__ We2, const float* __restrict__ be2) {
    const float* hin = useHn ? (const float*)g_hnb : (const float*)g_hb;
    float* outp = (float*)g_agb;
    int gw = (blockIdx.x * blockDim.x + threadIdx.x) >> 5;
    int node = gw >> 1;
    if (node >= N_NODES) return;
    int half = gw & 1;
    int lane = threadIdx.x & 31;
    int ch = half * 128 + lane * 4;

    float4 w[7];
#pragma unroll
    for (int k = 0; k < 7; k++) w[k] = *(const float4*)&We2[k * HID + ch];
    float4 bb = *(const float4*)&be2[ch];

    float4 acc = *(const float4*)&hin[node * HID + ch];   // self term

    int beg = g_rowptr[node], end = g_rowptr[node + 1];
    int j = beg;
    for (; j + 4 <= end; j += 4) {
        int s0 = g_csrs[j], s1 = g_csrs[j + 1], s2 = g_csrs[j + 2], s3 = g_csrs[j + 3];
        float4 e00 = g_eas[(j + 0) * 2], e01 = g_eas[(j + 0) * 2 + 1];
        float4 e10 = g_eas[(j + 1) * 2], e11 = g_eas[(j + 1) * 2 + 1];
        float4 e20 = g_eas[(j + 2) * 2], e21 = g_eas[(j + 2) * 2 + 1];
        float4 e30 = g_eas[(j + 3) * 2], e31 = g_eas[(j + 3) * 2 + 1];
        float4 h0 = *(const float4*)&hin[s0 * HID + ch];
        float4 h1 = *(const float4*)&hin[s1 * HID + ch];
        float4 h2 = *(const float4*)&hin[s2 * HID + ch];
        float4 h3 = *(const float4*)&hin[s3 * HID + ch];
        aggr_step(acc, w, bb, e00, e01, h0);
        aggr_step(acc, w, bb, e10, e11, h1);
        aggr_step(acc, w, bb, e20, e21, h2);
        aggr_step(acc, w, bb, e30, e31, h3);
    }
    for (; j < end; j++) {
        int s = g_csrs[j];
        float4 a0 = g_eas[j * 2], a1 = g_eas[j * 2 + 1];
        float4 h = *(const float4*)&hin[s * HID + ch];
        aggr_step(acc, w, bb, a0, a1, h);
    }
    *(float4*)&outp[node * HID + ch] = acc;
}

// ---------------- tf32 tensor-core GEMM: hout = relu(g_agb @ W + b) --------
// Block 128x128, 8 warps, warp tile 32x64 via mma.sync.m16n8k8.tf32.
// Custom smem layouts so A-frag = one LDS.128, B-frag = one LDS.64.
#define GBM 128
#define GBK 32
__global__ void __launch_bounds__(256)
k_gemm_tf32(int layer, const float* __restrict__ W, const float* __restrict__ b) {
    const float* A = (const float*)g_agb;
    float* hout = (layer == 2) ? (float*)g_hnb : (float*)g_hb;

    // As[mt(8)][ks(4)][lane(32)][slot(4)]  (tf32 bits)
    // Bs[nt(16)][ks(4)][lane(32)][slot(2)]
    __shared__ unsigned As[8 * 4 * 32 * 4];
    __shared__ unsigned Bs[16 * 4 * 32 * 2];

    int tid = threadIdx.x;
    int lane = tid & 31;
    int warp = tid >> 5;
    int wr = warp >> 1;          // 0..3 (warp row)
    int wc = warp & 1;           // 0..1 (warp col)
    int rowBase = blockIdx.y * GBM;
    int colBase = blockIdx.x * 128;

    float acc[2][8][4];
#pragma unroll
    for (int i = 0; i < 2; i++)
#pragma unroll
        for (int j = 0; j < 8; j++)
#pragma unroll
            for (int k = 0; k < 4; k++) acc[i][j][k] = 0.f;

    // A-load decomposition: thread handles col4 = tid&7 (4 cols), rows (tid>>3)+32*i
    int a_col4 = tid & 7;
    int a_ks = a_col4 >> 1;              // constant k-step for this thread
    int a_slot_hi = (a_col4 & 1) << 1;   // cc>>2 contribution to slot
    int a_row0 = tid >> 3;
    // B-load: thread handles col4 = tid&31 (4 cols), k = (tid>>5)+8*i
    int b_col4 = tid & 31;
    int b_nt = b_col4 >> 1;
    int b_nn_hi = (b_col4 & 1) << 2;     // nn = nn_hi + j
    int b_k0 = tid >> 5;

    for (int kt = 0; kt < HID; kt += GBK) {
        // ---- load A tile (128 rows x 32 k) into mma layout ----
#pragma unroll
        for (int i = 0; i < 4; i++) {
            int row = a_row0 + 32 * i;
            int grow = rowBase + row;
            float4 v = make_float4(0.f, 0.f, 0.f, 0.f);
            if (grow < N_NODES)
                v = *(const float4*)&A[grow * HID + kt + a_col4 * 4];
            int mt = row >> 4, rr = row & 15;
            int base = ((mt * 4 + a_ks) * 32 + ((rr & 7) << 2)) * 4 + ((rr >> 3) | a_slot_hi);
            As[base + 0 * 4] = to_tf32(v.x);
            As[base + 1 * 4] = to_tf32(v.y);
            As[base + 2 * 4] = to_tf32(v.z);
            As[base + 3 * 4] = to_tf32(v.w);
        }
        // ---- load B tile (32 k x 128 n) into mma layout ----
#pragma unroll
        for (int i = 0; i < 4; i++) {
            int k = b_k0 + 8 * i;
            float4 v = *(const float4*)&W[(kt + k) * HID + colBase + b_col4 * 4];
            int ks = k >> 3, kk3 = k & 3;
            int slot = (k & 7) >> 2;
            int base = ((b_nt * 4 + ks) * 32 + (b_nn_hi << 2) + kk3) * 2 + slot;
            Bs[base + 0 * 8] = to_tf32(v.x);   // nn step = +1 -> lane +4 -> idx +8
            Bs[base + 1 * 8] = to_tf32(v.y);
            Bs[base + 2 * 8] = to_tf32(v.z);
            Bs[base + 3 * 8] = to_tf32(v.w);
        }
        __syncthreads();

#pragma unroll
        for (int ks = 0; ks < 4; ks++) {
            unsigned af[2][4];
#pragma unroll
            for (int mtl = 0; mtl < 2; mtl++) {
                uint4 v = *(const uint4*)&As[(((wr * 2 + mtl) * 4 + ks) * 32 + lane) * 4];
                af[mtl][0] = v.x; af[mtl][1] = v.y; af[mtl][2] = v.z; af[mtl][3] = v.w;
            }
            unsigned bf[8][2];
#pragma unroll
            for (int ntl = 0; ntl < 8; ntl++) {
                uint2 v = *(const uint2*)&Bs[(((wc * 8 + ntl) * 4 + ks) * 32 + lane) * 2];
                bf[ntl][0] = v.x; bf[ntl][1] = v.y;
            }
#pragma unroll
            for (int mtl = 0; mtl < 2; mtl++)
#pragma unroll
                for (int ntl = 0; ntl < 8; ntl++) {
                    asm volatile(
                        "mma.sync.aligned.m16n8k8.row.col.f32.tf32.tf32.f32 "
                        "{%0,%1,%2,%3}, {%4,%5,%6,%7}, {%8,%9}, {%0,%1,%2,%3};"
                        : "+f"(acc[mtl][ntl][0]), "+f"(acc[mtl][ntl][1]),
                          "+f"(acc[mtl][ntl][2]), "+f"(acc[mtl][ntl][3])
                        : "r"(af[mtl][0]), "r"(af[mtl][1]),
                          "r"(af[mtl][2]), "r"(af[mtl][3]),
                          "r"(bf[ntl][0]), "r"(bf[ntl][1]));
                }
        }
        __syncthreads();
    }

    // ---- epilogue: bias + relu, float2 stores ----
    int gid = lane >> 2;       // groupID
    int tig = lane & 3;
#pragma unroll
    for (int mtl = 0; mtl < 2; mtl++) {
        int row0 = rowBase + (wr * 2 + mtl) * 16 + gid;
#pragma unroll
        for (int ntl = 0; ntl < 8; ntl++) {
            int col = colBase + (wc * 8 + ntl) * 8 + tig * 2;
            float2 bv = *(const float2*)&b[col];
            if (row0 < N_NODES) {
                float2 o;
                o.x = fmaxf(acc[mtl][ntl][0] + bv.x, 0.f);
                o.y = fmaxf(acc[mtl][ntl][1] + bv.y, 0.f);
                *(float2*)&hout[row0 * HID + col] = o;
            }
            if (row0 + 8 < N_NODES) {
                float2 o;
                o.x = fmaxf(acc[mtl][ntl][2] + bv.x, 0.f);
                o.y = fmaxf(acc[mtl][ntl][3] + bv.y, 0.f);
                *(float2*)&hout[(row0 + 8) * HID + col] = o;
            }
        }
    }
}

// ---------------- final: sigmoid(h @ Wend + bend) ----------------
__global__ void k_final(const float* __restrict__ Wend,
                        const float* __restrict__ bend,
                        float* __restrict__ out) {
    int lane = threadIdx.x & 31;
    int warp = threadIdx.x >> 5;
    int n = blockIdx.x * 8 + warp;
    if (n >= N_NODES) return;
    const float* h = (const float*)g_hb;
    float s = 0.f;
#pragma unroll
    for (int c = lane * 4; c < HID; c += 128) {
        float4 hv = *(const float4*)&h[n * HID + c];
        float4 wv = *(const float4*)&Wend[c];
        s += hv.x * wv.x + hv.y * wv.y + hv.z * wv.z + hv.w * wv.w;
    }
#pragma unroll
    for (int o = 16; o; o >>= 1) s += __shfl_xor_sync(0xffffffffu, s, o);
    if (lane == 0) out[n] = 1.f / (1.f + __expf(-(s + bend[0])));
}

// ---------------- host ----------------
extern "C" void kernel_launch(void* const* d_in, const int* in_sizes, int n_in,
                              void* d_out, int out_size) {
    const float* x    = (const float*)d_in[0];
    const void*  ei   = d_in[1];
    const float* ea   = (const float*)d_in[2];
    const float* We1  = (const float*)d_in[3];
    const float* be1  = (const float*)d_in[4];
    const float* W1   = (const float*)d_in[5];
    const float* b1   = (const float*)d_in[6];
    const float* We2  = (const float*)d_in[7];
    const float* be2  = (const float*)d_in[8];
    const float* W2   = (const float*)d_in[9];
    const float* b2   = (const float*)d_in[10];
    const float* Wend = (const float*)d_in[11];
    const float* bend = (const float*)d_in[12];
    float* out = (float*)d_out;

    void *p_deg = nullptr, *p_agb = nullptr;
    cudaGetSymbolAddress(&p_deg, g_deg);
    cudaGetSymbolAddress(&p_agb, g_agb);

    k_detect<<<1, 32>>>(ei);
    k_convert<<<(N_EDGES + 255) / 256, 256>>>(ei);

    // CSR build (by dst)
    cudaMemsetAsync(p_deg, 0, N_NODES * sizeof(int));
    k_hist<<<(N_EDGES + 255) / 256, 256>>>();
    k_part<<<SCAN_B, 256>>>();
    k_scanb<<<1, 256>>>();
    k_rowptr<<<SCAN_B, 256>>>();
    k_fill<<<(N_EDGES + 255) / 256, 256>>>(ea);

    // layer 1
    cudaMemsetAsync(p_agb, 0, N_NODES * 2 * sizeof(float));
    k_scatter1<<<(N_EDGES + 255) / 256, 256>>>(x, ea, We1, be1);
    k_layer1nn<<<N_NODES, 256>>>(x, W1, b1);

    // layer 2: pull-aggregate from g_hb, tf32 GEMM -> g_hnb
    k_aggr<<<(N_NODES * 2 * 32 + 255) / 256, 256>>>(0, We2, be2);
    k_gemm_tf32<<<dim3(2, (N_NODES + GBM - 1) / GBM), 256>>>(2, W2, b2);

    // layer 3: pull-aggregate from g_hnb, tf32 GEMM -> g_hb
    k_aggr<<<(N_NODES * 2 * 32 + 255) / 256, 256>>>(1, We2, be2);
    k_gemm_tf32<<<dim3(2, (N_NODES + GBM - 1) / GBM), 256>>>(3, W2, b2);

    k_final<<<(N_NODES + 7) / 8, 256>>>(Wend, bend, out);
}

// round 7
// speedup vs baseline: 1.3856x; 1.3856x over previous
#include <cuda_runtime.h>
#include <cuda_fp16.h>

#define N_NODES 50000
#define N_EDGES 1600000
#define HID 256
#define SCAN_B 196   // ceil(N_NODES/256)

// ---------------- device scratch (static, no allocs) ----------------
__device__ float4   g_agb[N_NODES*HID/4];   // aggr output (tf32 bits) / layer1 aggr (fp32)
__device__ __half   g_h16a[N_NODES*HID];    // h fp16 buffer A
__device__ __half   g_h16b[N_NODES*HID];    // h fp16 buffer B
__device__ unsigned g_W2t[65536];           // W2 in tf32 fragment order
__device__ int      g_deg[N_NODES];
__device__ int      g_rowptr[N_NODES + 1];
__device__ int      g_cur[N_NODES];
__device__ int      g_csrs[N_EDGES];        // src node, grouped by dst
__device__ float4   g_eas[N_EDGES * 2];     // edge attrs (7 + pad) in CSR order
__device__ int      g_bsum[SCAN_B];
__device__ int      g_boff[SCAN_B];
__device__ int      g_flag;                 // 1 = edge_index int64, 0 = int32

__device__ __forceinline__ void red_add_v2(float* a, float x, float y) {
    asm volatile("red.global.add.v2.f32 [%0], {%1,%2};"
                 :: "l"(a), "f"(x), "f"(y) : "memory");
}
__device__ __forceinline__ unsigned to_tf32(float v) {
    unsigned r;
    asm("cvt.rna.tf32.f32 %0, %1;" : "=r"(r) : "f"(v));
    return r;
}
__device__ __forceinline__ int edge_src(const void* ei, int i) {
    return g_flag ? (int)((const long long*)ei)[i] : ((const int*)ei)[i];
}
__device__ __forceinline__ int edge_dst(const void* ei, int i) {
    return g_flag ? (int)((const long long*)ei)[N_EDGES + i]
                  : ((const int*)ei)[N_EDGES + i];
}

// ---------------- dtype detection ----------------
__global__ void k_detect(const void* ei) {
    if (threadIdx.x == 0) {
        const long long* p = (const long long*)ei;
        int is64 = 1;
        for (int i = 0; i < 64; i++) {
            long long v = p[i];
            if (v < 0 || v >= N_NODES) { is64 = 0; break; }
        }
        g_flag = is64;
    }
}

// ---------------- W2 -> tf32 fragment table ----------------
// idx = ((ct*32 + ks)*32 + lane)*2 + slot
// value = tf32(W[k][n]), k = ks*8 + (lane&3) + slot*4, n = ct*8 + (lane>>2)
__global__ void k_prepW(const float* __restrict__ W) {
    int idx = blockIdx.x * 256 + threadIdx.x;
    int slot = idx & 1;
    int l    = (idx >> 1) & 31;
    int ks   = (idx >> 6) & 31;
    int ct   = idx >> 11;
    int k = ks * 8 + (l & 3) + slot * 4;
    int n = ct * 8 + (l >> 2);
    g_W2t[idx] = to_tf32(W[k * HID + n]);
}

// ---------------- CSR build ----------------
__global__ void k_hist(const void* ei) {
    int i = blockIdx.x * blockDim.x + threadIdx.x;
    if (i < N_EDGES) atomicAdd(&g_deg[edge_dst(ei, i)], 1);
}

__global__ void k_part() {
    __shared__ int sm[256];
    int t = threadIdx.x;
    int n = blockIdx.x * 256 + t;
    int v = (n < N_NODES) ? g_deg[n] : 0;
    sm[t] = v;
    __syncthreads();
    for (int o = 128; o; o >>= 1) {
        if (t < o) sm[t] += sm[t + o];
        __syncthreads();
    }
    if (t == 0) g_bsum[blockIdx.x] = sm[0];
}

__global__ void k_scanb() {
    __shared__ int sm[256];
    int t = threadIdx.x;
    int v = (t < SCAN_B) ? g_bsum[t] : 0;
    sm[t] = v;
    __syncthreads();
    for (int o = 1; o < 256; o <<= 1) {
        int u = (t >= o) ? sm[t - o] : 0;
        __syncthreads();
        sm[t] += u;
        __syncthreads();
    }
    if (t < SCAN_B) g_boff[t] = sm[t] - v;   // exclusive
    if (t == 0) g_rowptr[N_NODES] = N_EDGES;
}

__global__ void k_rowptr() {
    __shared__ int sm[256];
    int t = threadIdx.x;
    int n = blockIdx.x * 256 + t;
    int v = (n < N_NODES) ? g_deg[n] : 0;
    sm[t] = v;
    __syncthreads();
    for (int o = 1; o < 256; o <<= 1) {
        int u = (t >= o) ? sm[t - o] : 0;
        __syncthreads();
        sm[t] += u;
        __syncthreads();
    }
    if (n < N_NODES) {
        int r = g_boff[blockIdx.x] + sm[t] - v;
        g_rowptr[n] = r;
        g_cur[n] = r;
    }
}

__global__ void k_fill(const void* ei, const float* __restrict__ ea) {
    int e = blockIdx.x * blockDim.x + threadIdx.x;
    if (e >= N_EDGES) return;
    int d = edge_dst(ei, e);
    int pos = atomicAdd(&g_cur[d], 1);
    g_csrs[pos] = edge_src(ei, e);
    const float* a = ea + (size_t)e * 7;
    g_eas[pos * 2 + 0] = make_float4(a[0], a[1], a[2], a[3]);
    g_eas[pos * 2 + 1] = make_float4(a[4], a[5], a[6], 0.f);
}

// ---------------- layer 1 scatter (C = 2, atomic push) ----------------
__global__ void k_scatter1(const void* ei,
                           const float* __restrict__ x,
                           const float* __restrict__ ea,
                           const float* __restrict__ We1,
                           const float* __restrict__ be1) {
    int e = blockIdx.x * blockDim.x + threadIdx.x;
    if (e >= N_EDGES) return;
    float a[7];
#pragma unroll
    for (int k = 0; k < 7; k++) a[k] = ea[e * 7 + k];
    float e0 = __ldg(&be1[0]), e1 = __ldg(&be1[1]);
#pragma unroll
    for (int k = 0; k < 7; k++) {
        e0 += a[k] * __ldg(&We1[k * 2 + 0]);
        e1 += a[k] * __ldg(&We1[k * 2 + 1]);
    }
    int s = edge_src(ei, e), d = edge_dst(ei, e);
    float m0 = fmaxf(x[2 * s + 0] + e0, 0.f);
    float m1 = fmaxf(x[2 * s + 1] + e1, 0.f);
    red_add_v2(((float*)g_agb) + 2 * d, m0, m1);
}

// ---------------- layer 1 nn -> fp16 ----------------
__global__ void k_layer1nn(const float* __restrict__ x,
                           const float* __restrict__ W1,
                           const float* __restrict__ b1) {
    int n = blockIdx.x;
    int c = threadIdx.x;
    const float* ag = (const float*)g_agb;
    float a0 = x[2 * n + 0] + ag[2 * n + 0];
    float a1 = x[2 * n + 1] + ag[2 * n + 1];
    float v = b1[c] + a0 * W1[c] + a1 * W1[HID + c];
    g_h16a[n * HID + c] = __float2half(fmaxf(v, 0.f));
}

// ---------------- layers 2/3 aggregation ----------------
__device__ __forceinline__ float4 h16_to_f4(uint2 u) {
    float2 lo = __half22float2(*(const __half2*)&u.x);
    float2 hi = __half22float2(*(const __half2*)&u.y);
    return make_float4(lo.x, lo.y, hi.x, hi.y);
}

__device__ __forceinline__ void aggr_step(
    float4& acc, const float4* w, float4 bb,
    float4 a0, float4 a1, float4 h)
{
    float4 m = bb;
    m.x += a0.x * w[0].x; m.y += a0.x * w[0].y; m.z += a0.x * w[0].z; m.w += a0.x * w[0].w;
    m.x += a0.y * w[1].x; m.y += a0.y * w[1].y; m.z += a0.y * w[1].z; m.w += a0.y * w[1].w;
    m.x += a0.z * w[2].x; m.y += a0.z * w[2].y; m.z += a0.z * w[2].z; m.w += a0.z * w[2].w;
    m.x += a0.w * w[3].x; m.y += a0.w * w[3].y; m.z += a0.w * w[3].z; m.w += a0.w * w[3].w;
    m.x += a1.x * w[4].x; m.y += a1.x * w[4].y; m.z += a1.x * w[4].z; m.w += a1.x * w[4].w;
    m.x += a1.y * w[5].x; m.y += a1.y * w[5].y; m.z += a1.y * w[5].z; m.w += a1.y * w[5].w;
    m.x += a1.z * w[6].x; m.y += a1.z * w[6].y; m.z += a1.z * w[6].z; m.w += a1.z * w[6].w;
    acc.x += fmaxf(m.x + h.x, 0.f);
    acc.y += fmaxf(m.y + h.y, 0.f);
    acc.z += fmaxf(m.z + h.z, 0.f);
    acc.w += fmaxf(m.w + h.w, 0.f);
}

__global__ void __launch_bounds__(256)
k_aggr(int useB, const float* __restrict__ We2, const float* __restrict__ be2) {
    const __half* hin = useB ? g_h16b : g_h16a;
    int gw = (blockIdx.x * blockDim.x + threadIdx.x) >> 5;
    int node = gw >> 1;
    if (node >= N_NODES) return;
    int half = gw & 1;
    int lane = threadIdx.x & 31;
    int ch = half * 128 + lane * 4;

    float4 w[7];
#pragma unroll
    for (int k = 0; k < 7; k++) w[k] = *(const float4*)&We2[k * HID + ch];
    float4 bb = *(const float4*)&be2[ch];

    float4 acc = h16_to_f4(*(const uint2*)&g_h16a[0]);   // placeholder overwritten below
    acc = h16_to_f4(*(const uint2*)&hin[node * HID + ch]);  // self term

    int beg = g_rowptr[node], end = g_rowptr[node + 1];
    int j = beg;
    for (; j + 4 <= end; j += 4) {
        int s0 = g_csrs[j], s1 = g_csrs[j + 1], s2 = g_csrs[j + 2], s3 = g_csrs[j + 3];
        float4 e00 = g_eas[(j + 0) * 2], e01 = g_eas[(j + 0) * 2 + 1];
        float4 e10 = g_eas[(j + 1) * 2], e11 = g_eas[(j + 1) * 2 + 1];
        float4 e20 = g_eas[(j + 2) * 2], e21 = g_eas[(j + 2) * 2 + 1];
        float4 e30 = g_eas[(j + 3) * 2], e31 = g_eas[(j + 3) * 2 + 1];
        uint2 u0 = *(const uint2*)&hin[s0 * HID + ch];
        uint2 u1 = *(const uint2*)&hin[s1 * HID + ch];
        uint2 u2 = *(const uint2*)&hin[s2 * HID + ch];
        uint2 u3 = *(const uint2*)&hin[s3 * HID + ch];
        aggr_step(acc, w, bb, e00, e01, h16_to_f4(u0));
        aggr_step(acc, w, bb, e10, e11, h16_to_f4(u1));
        aggr_step(acc, w, bb, e20, e21, h16_to_f4(u2));
        aggr_step(acc, w, bb, e30, e31, h16_to_f4(u3));
    }
    for (; j < end; j++) {
        int s = g_csrs[j];
        float4 a0 = g_eas[j * 2], a1 = g_eas[j * 2 + 1];
        float4 h = h16_to_f4(*(const uint2*)&hin[s * HID + ch]);
        aggr_step(acc, w, bb, a0, a1, h);
    }
    *(uint4*)&((unsigned*)g_agb)[node * HID + ch] =
        make_uint4(to_tf32(acc.x), to_tf32(acc.y), to_tf32(acc.z), to_tf32(acc.w));
}

// ---------------- tf32 tensor-core GEMM ----------------
// Block 128x128, 8 warps, warp tile 32x64. A repack = LDG.128 + STS.128.
// B fragments loaded directly from g_W2t (L2-resident, 256KB).
__global__ void __launch_bounds__(256)
k_gemm_tc(int layer, const float* __restrict__ b) {
    const unsigned* A = (const unsigned*)g_agb;   // tf32 bits, row-major
    __half* hout = (layer == 2) ? g_h16b : g_h16a;

    __shared__ unsigned As[8 * 4 * 4 * 32];   // [mt][ks][slot][lane]

    int tid = threadIdx.x;
    int lane = tid & 31;
    int warp = tid >> 5;
    int wr = warp >> 1;
    int wc = warp & 1;
    int rowBase = blockIdx.y * 128;
    int colBase16 = blockIdx.x * 16;

    float acc[2][8][4];
#pragma unroll
    for (int i = 0; i < 2; i++)
#pragma unroll
        for (int j = 0; j < 8; j++)
#pragma unroll
            for (int k = 0; k < 4; k++) acc[i][j][k] = 0.f;

    int a_c0 = tid & 7;
    int a_row0 = tid >> 3;
    int a_ks = a_c0 >> 1;
    int a_slot_hi = (a_c0 & 1) << 1;

    for (int kt = 0; kt < HID; kt += 32) {
        // ---- A repack: LDG.128 + STS.128 ----
#pragma unroll
        for (int i = 0; i < 4; i++) {
            int row = a_row0 + 32 * i;
            int grow = rowBase + row;
            uint4 v = make_uint4(0u, 0u, 0u, 0u);
            if (grow < N_NODES)
                v = *(const uint4*)&A[grow * HID + kt + a_c0 * 4];
            int rr = row & 15, mt = row >> 4;
            int slot = (rr >> 3) | a_slot_hi;
            *(uint4*)&As[(((mt * 4 + a_ks) * 4 + slot) * 32 + (rr & 7) * 4)] = v;
        }
        __syncthreads();

        uint2 bf[8];
#pragma unroll
        for (int ntl = 0; ntl < 8; ntl++) {
            int ct = colBase16 + wc * 8 + ntl;
            bf[ntl] = *(const uint2*)&g_W2t[((ct * 32 + (kt >> 3)) * 32 + lane) * 2];
        }
#pragma unroll
        for (int ks = 0; ks < 4; ks++) {
            uint2 bfn[8];
            if (ks < 3) {
#pragma unroll
                for (int ntl = 0; ntl < 8; ntl++) {
                    int ct = colBase16 + wc * 8 + ntl;
                    bfn[ntl] = *(const uint2*)&g_W2t[((ct * 32 + (kt >> 3) + ks + 1) * 32 + lane) * 2];
                }
            }
            unsigned af[2][4];
#pragma unroll
            for (int mtl = 0; mtl < 2; mtl++) {
                int mt = wr * 2 + mtl;
#pragma unroll
                for (int s = 0; s < 4; s++)
                    af[mtl][s] = As[((mt * 4 + ks) * 4 + s) * 32 + lane];
            }
#pragma unroll
            for (int mtl = 0; mtl < 2; mtl++)
#pragma unroll
                for (int ntl = 0; ntl < 8; ntl++) {
                    asm volatile(
                        "mma.sync.aligned.m16n8k8.row.col.f32.tf32.tf32.f32 "
                        "{%0,%1,%2,%3}, {%4,%5,%6,%7}, {%8,%9}, {%0,%1,%2,%3};"
                        : "+f"(acc[mtl][ntl][0]), "+f"(acc[mtl][ntl][1]),
                          "+f"(acc[mtl][ntl][2]), "+f"(acc[mtl][ntl][3])
                        : "r"(af[mtl][0]), "r"(af[mtl][1]),
                          "r"(af[mtl][2]), "r"(af[mtl][3]),
                          "r"(bf[ntl].x), "r"(bf[ntl].y));
                }
            if (ks < 3) {
#pragma unroll
                for (int ntl = 0; ntl < 8; ntl++) bf[ntl] = bfn[ntl];
            }
        }
        __syncthreads();
    }

    // ---- epilogue: bias + relu -> fp16 half2 stores ----
    int gid = lane >> 2;
    int tig = lane & 3;
#pragma unroll
    for (int mtl = 0; mtl < 2; mtl++) {
        int row0 = rowBase + (wr * 2 + mtl) * 16 + gid;
#pragma unroll
        for (int ntl = 0; ntl < 8; ntl++) {
            int col = colBase16 * 8 + (wc * 8 + ntl) * 8 + tig * 2;
            float2 bv = *(const float2*)&b[col];
            if (row0 < N_NODES) {
                __half2 o = __floats2half2_rn(fmaxf(acc[mtl][ntl][0] + bv.x, 0.f),
                                              fmaxf(acc[mtl][ntl][1] + bv.y, 0.f));
                *(__half2*)&hout[row0 * HID + col] = o;
            }
            if (row0 + 8 < N_NODES) {
                __half2 o = __floats2half2_rn(fmaxf(acc[mtl][ntl][2] + bv.x, 0.f),
                                              fmaxf(acc[mtl][ntl][3] + bv.y, 0.f));
                *(__half2*)&hout[(row0 + 8) * HID + col] = o;
            }
        }
    }
}

// ---------------- final: sigmoid(h @ Wend + bend) ----------------
__global__ void k_final(const float* __restrict__ Wend,
                        const float* __restrict__ bend,
                        float* __restrict__ out) {
    int lane = threadIdx.x & 31;
    int warp = threadIdx.x >> 5;
    int n = blockIdx.x * 8 + warp;
    if (n >= N_NODES) return;
    float s = 0.f;
#pragma unroll
    for (int c = lane * 4; c < HID; c += 128) {
        float4 hv = h16_to_f4(*(const uint2*)&g_h16a[n * HID + c]);
        float4 wv = *(const float4*)&Wend[c];
        s += hv.x * wv.x + hv.y * wv.y + hv.z * wv.z + hv.w * wv.w;
    }
#pragma unroll
    for (int o = 16; o; o >>= 1) s += __shfl_xor_sync(0xffffffffu, s, o);
    if (lane == 0) out[n] = 1.f / (1.f + __expf(-(s + bend[0])));
}

// ---------------- host ----------------
extern "C" void kernel_launch(void* const* d_in, const int* in_sizes, int n_in,
                              void* d_out, int out_size) {
    const float* x    = (const float*)d_in[0];
    const void*  ei   = d_in[1];
    const float* ea   = (const float*)d_in[2];
    const float* We1  = (const float*)d_in[3];
    const float* be1  = (const float*)d_in[4];
    const float* W1   = (const float*)d_in[5];
    const float* b1   = (const float*)d_in[6];
    const float* We2  = (const float*)d_in[7];
    const float* be2  = (const float*)d_in[8];
    const float* W2   = (const float*)d_in[9];
    const float* b2   = (const float*)d_in[10];
    const float* Wend = (const float*)d_in[11];
    const float* bend = (const float*)d_in[12];
    float* out = (float*)d_out;

    void *p_deg = nullptr, *p_agb = nullptr;
    cudaGetSymbolAddress(&p_deg, g_deg);
    cudaGetSymbolAddress(&p_agb, g_agb);

    k_detect<<<1, 32>>>(ei);
    k_prepW<<<256, 256>>>(W2);

    // CSR build (by dst)
    cudaMemsetAsync(p_deg, 0, N_NODES * sizeof(int));
    k_hist<<<(N_EDGES + 255) / 256, 256>>>(ei);
    k_part<<<SCAN_B, 256>>>();
    k_scanb<<<1, 256>>>();
    k_rowptr<<<SCAN_B, 256>>>();
    k_fill<<<(N_EDGES + 255) / 256, 256>>>(ei, ea);

    // layer 1
    cudaMemsetAsync(p_agb, 0, N_NODES * 2 * sizeof(float));
    k_scatter1<<<(N_EDGES + 255) / 256, 256>>>(ei, x, ea, We1, be1);
    k_layer1nn<<<N_NODES, 256>>>(x, W1, b1);

    // layer 2
    k_aggr<<<(N_NODES * 2 * 32 + 255) / 256, 256>>>(0, We2, be2);
    k_gemm_tc<<<dim3(2, (N_NODES + 127) / 128), 256>>>(2, b2);

    // layer 3
    k_aggr<<<(N_NODES * 2 * 32 + 255) / 256, 256>>>(1, We2, be2);
    k_gemm_tc<<<dim3(2, (N_NODES + 127) / 128), 256>>>(3, b2);

    k_final<<<(N_NODES + 7) / 8, 256>>>(Wend, bend, out);
}

// round 8
// speedup vs baseline: 1.6960x; 1.2240x over previous
#include <cuda_runtime.h>
#include <cuda_fp16.h>

#define N_NODES 50000
#define N_EDGES 1600000
#define HID 256
#define SCAN_B 196   // ceil(N_NODES/256)

// ---------------- device scratch (static, no allocs) ----------------
__device__ float4   g_agb[N_NODES*HID/4];   // aggr output (tf32 bits) / layer1 aggr (fp32)
__device__ __half   g_h16a[N_NODES*HID];    // h fp16 buffer A
__device__ __half   g_h16b[N_NODES*HID];    // h fp16 buffer B
__device__ unsigned g_W2t[65536];           // W2 in tf32 fragment order
__device__ int      g_deg[N_NODES];
__device__ int      g_rowptr[N_NODES + 1];
__device__ int      g_cur[N_NODES];
__device__ int      g_csrs[N_EDGES];        // src node, grouped by dst
__device__ uint4    g_eah[N_EDGES * 2];     // edge attrs as duplicated half2, CSR order
__device__ int      g_bsum[SCAN_B];
__device__ int      g_boff[SCAN_B];
__device__ int      g_flag;                 // 1 = edge_index int64, 0 = int32

__device__ __forceinline__ void red_add_v2(float* a, float x, float y) {
    asm volatile("red.global.add.v2.f32 [%0], {%1,%2};"
                 :: "l"(a), "f"(x), "f"(y) : "memory");
}
__device__ __forceinline__ unsigned to_tf32(float v) {
    unsigned r;
    asm("cvt.rna.tf32.f32 %0, %1;" : "=r"(r) : "f"(v));
    return r;
}
__device__ __forceinline__ int edge_src(const void* ei, int i) {
    return g_flag ? (int)((const long long*)ei)[i] : ((const int*)ei)[i];
}
__device__ __forceinline__ int edge_dst(const void* ei, int i) {
    return g_flag ? (int)((const long long*)ei)[N_EDGES + i]
                  : ((const int*)ei)[N_EDGES + i];
}

// ---------------- dtype detection ----------------
__global__ void k_detect(const void* ei) {
    if (threadIdx.x == 0) {
        const long long* p = (const long long*)ei;
        int is64 = 1;
        for (int i = 0; i < 64; i++) {
            long long v = p[i];
            if (v < 0 || v >= N_NODES) { is64 = 0; break; }
        }
        g_flag = is64;
    }
}

// ---------------- W2 -> tf32 fragment table ----------------
__global__ void k_prepW(const float* __restrict__ W) {
    int idx = blockIdx.x * 256 + threadIdx.x;
    int slot = idx & 1;
    int l    = (idx >> 1) & 31;
    int ks   = (idx >> 6) & 31;
    int ct   = idx >> 11;
    int k = ks * 8 + (l & 3) + slot * 4;
    int n = ct * 8 + (l >> 2);
    g_W2t[idx] = to_tf32(W[k * HID + n]);
}

// ---------------- CSR build ----------------
__global__ void k_hist(const void* ei) {
    int i = blockIdx.x * blockDim.x + threadIdx.x;
    if (i < N_EDGES) atomicAdd(&g_deg[edge_dst(ei, i)], 1);
}

__global__ void k_part() {
    __shared__ int sm[256];
    int t = threadIdx.x;
    int n = blockIdx.x * 256 + t;
    int v = (n < N_NODES) ? g_deg[n] : 0;
    sm[t] = v;
    __syncthreads();
    for (int o = 128; o; o >>= 1) {
        if (t < o) sm[t] += sm[t + o];
        __syncthreads();
    }
    if (t == 0) g_bsum[blockIdx.x] = sm[0];
}

__global__ void k_scanb() {
    __shared__ int sm[256];
    int t = threadIdx.x;
    int v = (t < SCAN_B) ? g_bsum[t] : 0;
    sm[t] = v;
    __syncthreads();
    for (int o = 1; o < 256; o <<= 1) {
        int u = (t >= o) ? sm[t - o] : 0;
        __syncthreads();
        sm[t] += u;
        __syncthreads();
    }
    if (t < SCAN_B) g_boff[t] = sm[t] - v;   // exclusive
    if (t == 0) g_rowptr[N_NODES] = N_EDGES;
}

__global__ void k_rowptr() {
    __shared__ int sm[256];
    int t = threadIdx.x;
    int n = blockIdx.x * 256 + t;
    int v = (n < N_NODES) ? g_deg[n] : 0;
    sm[t] = v;
    __syncthreads();
    for (int o = 1; o < 256; o <<= 1) {
        int u = (t >= o) ? sm[t - o] : 0;
        __syncthreads();
        sm[t] += u;
        __syncthreads();
    }
    if (n < N_NODES) {
        int r = g_boff[blockIdx.x] + sm[t] - v;
        g_rowptr[n] = r;
        g_cur[n] = r;
    }
}

// fill CSR: src ids + edge attrs as duplicated half2 (a_k, a_k), CSR order
__global__ void k_fill(const void* ei, const float* __restrict__ ea) {
    int e = blockIdx.x * blockDim.x + threadIdx.x;
    if (e >= N_EDGES) return;
    int d = edge_dst(ei, e);
    int pos = atomicAdd(&g_cur[d], 1);
    g_csrs[pos] = edge_src(ei, e);
    const float* a = ea + (size_t)e * 7;
    uint4 v0, v1;
    __half2* p0 = (__half2*)&v0;
    __half2* p1 = (__half2*)&v1;
    p0[0] = __float2half2_rn(a[0]);
    p0[1] = __float2half2_rn(a[1]);
    p0[2] = __float2half2_rn(a[2]);
    p0[3] = __float2half2_rn(a[3]);
    p1[0] = __float2half2_rn(a[4]);
    p1[1] = __float2half2_rn(a[5]);
    p1[2] = __float2half2_rn(a[6]);
    p1[3] = __float2half2_rn(0.f);
    g_eah[pos * 2 + 0] = v0;
    g_eah[pos * 2 + 1] = v1;
}

// ---------------- layer 1 scatter (C = 2, atomic push) ----------------
__global__ void k_scatter1(const void* ei,
                           const float* __restrict__ x,
                           const float* __restrict__ ea,
                           const float* __restrict__ We1,
                           const float* __restrict__ be1) {
    int e = blockIdx.x * blockDim.x + threadIdx.x;
    if (e >= N_EDGES) return;
    float a[7];
#pragma unroll
    for (int k = 0; k < 7; k++) a[k] = ea[e * 7 + k];
    float e0 = __ldg(&be1[0]), e1 = __ldg(&be1[1]);
#pragma unroll
    for (int k = 0; k < 7; k++) {
        e0 += a[k] * __ldg(&We1[k * 2 + 0]);
        e1 += a[k] * __ldg(&We1[k * 2 + 1]);
    }
    int s = edge_src(ei, e), d = edge_dst(ei, e);
    float m0 = fmaxf(x[2 * s + 0] + e0, 0.f);
    float m1 = fmaxf(x[2 * s + 1] + e1, 0.f);
    red_add_v2(((float*)g_agb) + 2 * d, m0, m1);
}

// ---------------- layer 1 nn -> fp16 ----------------
__global__ void k_layer1nn(const float* __restrict__ x,
                           const float* __restrict__ W1,
                           const float* __restrict__ b1) {
    int n = blockIdx.x;
    int c = threadIdx.x;
    const float* ag = (const float*)g_agb;
    float a0 = x[2 * n + 0] + ag[2 * n + 0];
    float a1 = x[2 * n + 1] + ag[2 * n + 1];
    float v = b1[c] + a0 * W1[c] + a1 * W1[HID + c];
    g_h16a[n * HID + c] = __float2half(fmaxf(v, 0.f));
}

// ---------------- layers 2/3 aggregation: one warp/node, half2 math --------
// Each lane owns 8 channels. Edge emb computed in HFMA2 from duplicated attrs,
// msg relu in half2, accumulation in fp32.
__device__ __forceinline__ void aggr_edge_h2(
    float* accf, const __half2 wh[7][4], const __half2 bh[4],
    uint4 ua, uint4 ub, uint4 uh)
{
    const __half2* ah = (const __half2*)&ua;   // a0..a3 (dup)
    const __half2* ah2 = (const __half2*)&ub;  // a4..a6 (dup)
    const __half2* h2 = (const __half2*)&uh;   // 8 fp16 channels
    __half2 zero = __float2half2_rn(0.f);
#pragma unroll
    for (int c = 0; c < 4; c++) {
        __half2 m = bh[c];
        m = __hfma2(ah[0], wh[0][c], m);
        m = __hfma2(ah[1], wh[1][c], m);
        m = __hfma2(ah[2], wh[2][c], m);
        m = __hfma2(ah[3], wh[3][c], m);
        m = __hfma2(ah2[0], wh[4][c], m);
        m = __hfma2(ah2[1], wh[5][c], m);
        m = __hfma2(ah2[2], wh[6][c], m);
        m = __hadd2(m, h2[c]);
        m = __hmax2(m, zero);
        float2 f = __half22float2(m);
        accf[2 * c + 0] += f.x;
        accf[2 * c + 1] += f.y;
    }
}

__global__ void __launch_bounds__(256)
k_aggr(int useB, const float* __restrict__ We2, const float* __restrict__ be2) {
    const __half* hin = useB ? g_h16b : g_h16a;
    int node = (blockIdx.x * blockDim.x + threadIdx.x) >> 5;
    if (node >= N_NODES) return;
    int lane = threadIdx.x & 31;
    int ch = lane * 8;

    // weights as half2: wh[k][c] covers channels ch+2c, ch+2c+1
    __half2 wh[7][4];
#pragma unroll
    for (int k = 0; k < 7; k++) {
        float4 lo = *(const float4*)&We2[k * HID + ch];
        float4 hi = *(const float4*)&We2[k * HID + ch + 4];
        wh[k][0] = __floats2half2_rn(lo.x, lo.y);
        wh[k][1] = __floats2half2_rn(lo.z, lo.w);
        wh[k][2] = __floats2half2_rn(hi.x, hi.y);
        wh[k][3] = __floats2half2_rn(hi.z, hi.w);
    }
    __half2 bh[4];
    {
        float4 lo = *(const float4*)&be2[ch];
        float4 hi = *(const float4*)&be2[ch + 4];
        bh[0] = __floats2half2_rn(lo.x, lo.y);
        bh[1] = __floats2half2_rn(lo.z, lo.w);
        bh[2] = __floats2half2_rn(hi.x, hi.y);
        bh[3] = __floats2half2_rn(hi.z, hi.w);
    }

    // self term (fp32 accumulators)
    float accf[8];
    {
        uint4 uh = *(const uint4*)&hin[node * HID + ch];
        const __half2* h2 = (const __half2*)&uh;
#pragma unroll
        for (int c = 0; c < 4; c++) {
            float2 f = __half22float2(h2[c]);
            accf[2 * c + 0] = f.x;
            accf[2 * c + 1] = f.y;
        }
    }

    int beg = g_rowptr[node], end = g_rowptr[node + 1];
    int j = beg;
    for (; j + 4 <= end; j += 4) {
        int s0 = g_csrs[j], s1 = g_csrs[j + 1], s2 = g_csrs[j + 2], s3 = g_csrs[j + 3];
        uint4 a00 = g_eah[(j + 0) * 2], a01 = g_eah[(j + 0) * 2 + 1];
        uint4 a10 = g_eah[(j + 1) * 2], a11 = g_eah[(j + 1) * 2 + 1];
        uint4 a20 = g_eah[(j + 2) * 2], a21 = g_eah[(j + 2) * 2 + 1];
        uint4 a30 = g_eah[(j + 3) * 2], a31 = g_eah[(j + 3) * 2 + 1];
        uint4 h0 = *(const uint4*)&hin[s0 * HID + ch];
        uint4 h1 = *(const uint4*)&hin[s1 * HID + ch];
        uint4 h2 = *(const uint4*)&hin[s2 * HID + ch];
        uint4 h3 = *(const uint4*)&hin[s3 * HID + ch];
        aggr_edge_h2(accf, wh, bh, a00, a01, h0);
        aggr_edge_h2(accf, wh, bh, a10, a11, h1);
        aggr_edge_h2(accf, wh, bh, a20, a21, h2);
        aggr_edge_h2(accf, wh, bh, a30, a31, h3);
    }
    for (; j < end; j++) {
        int s = g_csrs[j];
        uint4 a0 = g_eah[j * 2], a1 = g_eah[j * 2 + 1];
        uint4 h = *(const uint4*)&hin[s * HID + ch];
        aggr_edge_h2(accf, wh, bh, a0, a1, h);
    }

    // store tf32 bits for the GEMM
    unsigned* outp = (unsigned*)g_agb + node * HID + ch;
    *(uint4*)outp =
        make_uint4(to_tf32(accf[0]), to_tf32(accf[1]), to_tf32(accf[2]), to_tf32(accf[3]));
    *(uint4*)(outp + 4) =
        make_uint4(to_tf32(accf[4]), to_tf32(accf[5]), to_tf32(accf[6]), to_tf32(accf[7]));
}

// ---------------- tf32 tensor-core GEMM ----------------
__global__ void __launch_bounds__(256)
k_gemm_tc(int layer, const float* __restrict__ b) {
    const unsigned* A = (const unsigned*)g_agb;   // tf32 bits, row-major
    __half* hout = (layer == 2) ? g_h16b : g_h16a;

    __shared__ unsigned As[8 * 4 * 4 * 32];   // [mt][ks][slot][lane]

    int tid = threadIdx.x;
    int lane = tid & 31;
    int warp = tid >> 5;
    int wr = warp >> 1;
    int wc = warp & 1;
    int rowBase = blockIdx.y * 128;
    int colBase16 = blockIdx.x * 16;

    float acc[2][8][4];
#pragma unroll
    for (int i = 0; i < 2; i++)
#pragma unroll
        for (int j = 0; j < 8; j++)
#pragma unroll
            for (int k = 0; k < 4; k++) acc[i][j][k] = 0.f;

    int a_c0 = tid & 7;
    int a_row0 = tid >> 3;
    int a_ks = a_c0 >> 1;
    int a_slot_hi = (a_c0 & 1) << 1;

    for (int kt = 0; kt < HID; kt += 32) {
#pragma unroll
        for (int i = 0; i < 4; i++) {
            int row = a_row0 + 32 * i;
            int grow = rowBase + row;
            uint4 v = make_uint4(0u, 0u, 0u, 0u);
            if (grow < N_NODES)
                v = *(const uint4*)&A[grow * HID + kt + a_c0 * 4];
            int rr = row & 15, mt = row >> 4;
            int slot = (rr >> 3) | a_slot_hi;
            *(uint4*)&As[(((mt * 4 + a_ks) * 4 + slot) * 32 + (rr & 7) * 4)] = v;
        }
        __syncthreads();

        uint2 bf[8];
#pragma unroll
        for (int ntl = 0; ntl < 8; ntl++) {
            int ct = colBase16 + wc * 8 + ntl;
            bf[ntl] = *(const uint2*)&g_W2t[((ct * 32 + (kt >> 3)) * 32 + lane) * 2];
        }
#pragma unroll
        for (int ks = 0; ks < 4; ks++) {
            uint2 bfn[8];
            if (ks < 3) {
#pragma unroll
                for (int ntl = 0; ntl < 8; ntl++) {
                    int ct = colBase16 + wc * 8 + ntl;
                    bfn[ntl] = *(const uint2*)&g_W2t[((ct * 32 + (kt >> 3) + ks + 1) * 32 + lane) * 2];
                }
            }
            unsigned af[2][4];
#pragma unroll
            for (int mtl = 0; mtl < 2; mtl++) {
                int mt = wr * 2 + mtl;
#pragma unroll
                for (int s = 0; s < 4; s++)
                    af[mtl][s] = As[((mt * 4 + ks) * 4 + s) * 32 + lane];
            }
#pragma unroll
            for (int mtl = 0; mtl < 2; mtl++)
#pragma unroll
                for (int ntl = 0; ntl < 8; ntl++) {
                    asm volatile(
                        "mma.sync.aligned.m16n8k8.row.col.f32.tf32.tf32.f32 "
                        "{%0,%1,%2,%3}, {%4,%5,%6,%7}, {%8,%9}, {%0,%1,%2,%3};"
                        : "+f"(acc[mtl][ntl][0]), "+f"(acc[mtl][ntl][1]),
                          "+f"(acc[mtl][ntl][2]), "+f"(acc[mtl][ntl][3])
                        : "r"(af[mtl][0]), "r"(af[mtl][1]),
                          "r"(af[mtl][2]), "r"(af[mtl][3]),
                          "r"(bf[ntl].x), "r"(bf[ntl].y));
                }
            if (ks < 3) {
#pragma unroll
                for (int ntl = 0; ntl < 8; ntl++) bf[ntl] = bfn[ntl];
            }
        }
        __syncthreads();
    }

    int gid = lane >> 2;
    int tig = lane & 3;
#pragma unroll
    for (int mtl = 0; mtl < 2; mtl++) {
        int row0 = rowBase + (wr * 2 + mtl) * 16 + gid;
#pragma unroll
        for (int ntl = 0; ntl < 8; ntl++) {
            int col = colBase16 * 8 + (wc * 8 + ntl) * 8 + tig * 2;
            float2 bv = *(const float2*)&b[col];
            if (row0 < N_NODES) {
                __half2 o = __floats2half2_rn(fmaxf(acc[mtl][ntl][0] + bv.x, 0.f),
                                              fmaxf(acc[mtl][ntl][1] + bv.y, 0.f));
                *(__half2*)&hout[row0 * HID + col] = o;
            }
            if (row0 + 8 < N_NODES) {
                __half2 o = __floats2half2_rn(fmaxf(acc[mtl][ntl][2] + bv.x, 0.f),
                                              fmaxf(acc[mtl][ntl][3] + bv.y, 0.f));
                *(__half2*)&hout[(row0 + 8) * HID + col] = o;
            }
        }
    }
}

// ---------------- final: sigmoid(h @ Wend + bend) ----------------
__global__ void k_final(const float* __restrict__ Wend,
                        const float* __restrict__ bend,
                        float* __restrict__ out) {
    int lane = threadIdx.x & 31;
    int warp = threadIdx.x >> 5;
    int n = blockIdx.x * 8 + warp;
    if (n >= N_NODES) return;
    float s = 0.f;
#pragma unroll
    for (int c = lane * 8; c < HID; c += 256) {
        uint4 uh = *(const uint4*)&g_h16a[n * HID + c];
        const __half2* h2 = (const __half2*)&uh;
        float4 w0 = *(const float4*)&Wend[c];
        float4 w1 = *(const float4*)&Wend[c + 4];
        float2 f0 = __half22float2(h2[0]);
        float2 f1 = __half22float2(h2[1]);
        float2 f2 = __half22float2(h2[2]);
        float2 f3 = __half22float2(h2[3]);
        s += f0.x * w0.x + f0.y * w0.y + f1.x * w0.z + f1.y * w0.w;
        s += f2.x * w1.x + f2.y * w1.y + f3.x * w1.z + f3.y * w1.w;
    }
#pragma unroll
    for (int o = 16; o; o >>= 1) s += __shfl_xor_sync(0xffffffffu, s, o);
    if (lane == 0) out[n] = 1.f / (1.f + __expf(-(s + bend[0])));
}

// ---------------- host ----------------
extern "C" void kernel_launch(void* const* d_in, const int* in_sizes, int n_in,
                              void* d_out, int out_size) {
    const float* x    = (const float*)d_in[0];
    const void*  ei   = d_in[1];
    const float* ea   = (const float*)d_in[2];
    const float* We1  = (const float*)d_in[3];
    const float* be1  = (const float*)d_in[4];
    const float* W1   = (const float*)d_in[5];
    const float* b1   = (const float*)d_in[6];
    const float* We2  = (const float*)d_in[7];
    const float* be2  = (const float*)d_in[8];
    const float* W2   = (const float*)d_in[9];
    const float* b2   = (const float*)d_in[10];
    const float* Wend = (const float*)d_in[11];
    const float* bend = (const float*)d_in[12];
    float* out = (float*)d_out;

    void *p_deg = nullptr, *p_agb = nullptr;
    cudaGetSymbolAddress(&p_deg, g_deg);
    cudaGetSymbolAddress(&p_agb, g_agb);

    k_detect<<<1, 32>>>(ei);
    k_prepW<<<256, 256>>>(W2);

    // CSR build (by dst)
    cudaMemsetAsync(p_deg, 0, N_NODES * sizeof(int));
    k_hist<<<(N_EDGES + 255) / 256, 256>>>(ei);
    k_part<<<SCAN_B, 256>>>();
    k_scanb<<<1, 256>>>();
    k_rowptr<<<SCAN_B, 256>>>();
    k_fill<<<(N_EDGES + 255) / 256, 256>>>(ei, ea);

    // layer 1
    cudaMemsetAsync(p_agb, 0, N_NODES * 2 * sizeof(float));
    k_scatter1<<<(N_EDGES + 255) / 256, 256>>>(ei, x, ea, We1, be1);
    k_layer1nn<<<N_NODES, 256>>>(x, W1, b1);

    // layer 2
    k_aggr<<<(N_NODES * 32 + 255) / 256, 256>>>(0, We2, be2);
    k_gemm_tc<<<dim3(2, (N_NODES + 127) / 128), 256>>>(2, b2);

    // layer 3
    k_aggr<<<(N_NODES * 32 + 255) / 256, 256>>>(1, We2, be2);
    k_gemm_tc<<<dim3(2, (N_NODES + 127) / 128), 256>>>(3, b2);

    k_final<<<(N_NODES + 7) / 8, 256>>>(Wend, bend, out);
}

// round 9
// speedup vs baseline: 1.7154x; 1.0115x over previous
#include <cuda_runtime.h>
#include <cuda_fp16.h>

#define N_NODES 50000
#define N_EDGES 1600000
#define HID 256
#define SCAN_B 196   // ceil(N_NODES/256)

// ---------------- device scratch (static, no allocs) ----------------
__device__ float4   g_agb[N_NODES*HID/4];   // aggr output (tf32 bits) / layer1 aggr (fp32)
__device__ __half   g_h16a[N_NODES*HID];    // h fp16 buffer A
__device__ __half   g_h16b[N_NODES*HID];    // h fp16 buffer B
__device__ unsigned g_W2t[65536];           // W2 in tf32 fragment order
__device__ int      g_deg[N_NODES];
__device__ int      g_rowptr[N_NODES + 1];
__device__ int      g_cur[N_NODES];
__device__ int      g_csrs[N_EDGES];        // src node, grouped by dst
__device__ uint4    g_eah[N_EDGES * 2];     // edge attrs as duplicated half2, CSR order
__device__ int      g_bsum[SCAN_B];
__device__ int      g_boff[SCAN_B];
__device__ int      g_flag;                 // 1 = edge_index int64, 0 = int32

__device__ __forceinline__ void red_add_v2(float* a, float x, float y) {
    asm volatile("red.global.add.v2.f32 [%0], {%1,%2};"
                 :: "l"(a), "f"(x), "f"(y) : "memory");
}
__device__ __forceinline__ unsigned to_tf32(float v) {
    unsigned r;
    asm("cvt.rna.tf32.f32 %0, %1;" : "=r"(r) : "f"(v));
    return r;
}
__device__ __forceinline__ int edge_src(const void* ei, int i) {
    return g_flag ? (int)((const long long*)ei)[i] : ((const int*)ei)[i];
}
__device__ __forceinline__ int edge_dst(const void* ei, int i) {
    return g_flag ? (int)((const long long*)ei)[N_EDGES + i]
                  : ((const int*)ei)[N_EDGES + i];
}

// ---------------- fused: dtype detect + W2 -> tf32 fragment table ----------
__global__ void k_prep(const void* ei, const float* __restrict__ W) {
    if (blockIdx.x == 0 && threadIdx.x == 0) {
        const long long* p = (const long long*)ei;
        int is64 = 1;
        for (int i = 0; i < 64; i++) {
            long long v = p[i];
            if (v < 0 || v >= N_NODES) { is64 = 0; break; }
        }
        g_flag = is64;
    }
    int idx = blockIdx.x * 256 + threadIdx.x;
    int slot = idx & 1;
    int l    = (idx >> 1) & 31;
    int ks   = (idx >> 6) & 31;
    int ct   = idx >> 11;
    int k = ks * 8 + (l & 3) + slot * 4;
    int n = ct * 8 + (l >> 2);
    g_W2t[idx] = to_tf32(W[k * HID + n]);
}

// ---------------- CSR build ----------------
__global__ void k_hist(const void* ei) {
    int i = blockIdx.x * blockDim.x + threadIdx.x;
    if (i < N_EDGES) atomicAdd(&g_deg[edge_dst(ei, i)], 1);
}

__global__ void k_part() {
    __shared__ int sm[256];
    int t = threadIdx.x;
    int n = blockIdx.x * 256 + t;
    int v = (n < N_NODES) ? g_deg[n] : 0;
    sm[t] = v;
    __syncthreads();
    for (int o = 128; o; o >>= 1) {
        if (t < o) sm[t] += sm[t + o];
        __syncthreads();
    }
    if (t == 0) g_bsum[blockIdx.x] = sm[0];
}

__global__ void k_scanb() {
    __shared__ int sm[256];
    int t = threadIdx.x;
    int v = (t < SCAN_B) ? g_bsum[t] : 0;
    sm[t] = v;
    __syncthreads();
    for (int o = 1; o < 256; o <<= 1) {
        int u = (t >= o) ? sm[t - o] : 0;
        __syncthreads();
        sm[t] += u;
        __syncthreads();
    }
    if (t < SCAN_B) g_boff[t] = sm[t] - v;   // exclusive
    if (t == 0) g_rowptr[N_NODES] = N_EDGES;
}

__global__ void k_rowptr() {
    __shared__ int sm[256];
    int t = threadIdx.x;
    int n = blockIdx.x * 256 + t;
    int v = (n < N_NODES) ? g_deg[n] : 0;
    sm[t] = v;
    __syncthreads();
    for (int o = 1; o < 256; o <<= 1) {
        int u = (t >= o) ? sm[t - o] : 0;
        __syncthreads();
        sm[t] += u;
        __syncthreads();
    }
    if (n < N_NODES) {
        int r = g_boff[blockIdx.x] + sm[t] - v;
        g_rowptr[n] = r;
        g_cur[n] = r;
    }
}

// ---------------- fused fill + layer1 scatter ----------------
// Builds CSR (src ids + duplicated-half2 attrs) AND does the layer-1
// 2-channel message scatter from the same ea row read.
__global__ void k_fillscat(const void* ei, const float* __restrict__ ea,
                           const float* __restrict__ x,
                           const float* __restrict__ We1,
                           const float* __restrict__ be1) {
    int e = blockIdx.x * blockDim.x + threadIdx.x;
    if (e >= N_EDGES) return;
    int s = edge_src(ei, e);
    int d = edge_dst(ei, e);
    float a[7];
    const float* ap = ea + (size_t)e * 7;
#pragma unroll
    for (int k = 0; k < 7; k++) a[k] = ap[k];

    // CSR fill
    int pos = atomicAdd(&g_cur[d], 1);
    g_csrs[pos] = s;
    uint4 v0, v1;
    __half2* p0 = (__half2*)&v0;
    __half2* p1 = (__half2*)&v1;
    p0[0] = __float2half2_rn(a[0]);
    p0[1] = __float2half2_rn(a[1]);
    p0[2] = __float2half2_rn(a[2]);
    p0[3] = __float2half2_rn(a[3]);
    p1[0] = __float2half2_rn(a[4]);
    p1[1] = __float2half2_rn(a[5]);
    p1[2] = __float2half2_rn(a[6]);
    p1[3] = __float2half2_rn(0.f);
    g_eah[pos * 2 + 0] = v0;
    g_eah[pos * 2 + 1] = v1;

    // layer-1 scatter (C = 2)
    float e0 = __ldg(&be1[0]), e1 = __ldg(&be1[1]);
#pragma unroll
    for (int k = 0; k < 7; k++) {
        e0 += a[k] * __ldg(&We1[k * 2 + 0]);
        e1 += a[k] * __ldg(&We1[k * 2 + 1]);
    }
    float m0 = fmaxf(x[2 * s + 0] + e0, 0.f);
    float m1 = fmaxf(x[2 * s + 1] + e1, 0.f);
    red_add_v2(((float*)g_agb) + 2 * d, m0, m1);
}

// ---------------- layer 1 nn -> fp16 ----------------
__global__ void k_layer1nn(const float* __restrict__ x,
                           const float* __restrict__ W1,
                           const float* __restrict__ b1) {
    int n = blockIdx.x;
    int c = threadIdx.x;
    const float* ag = (const float*)g_agb;
    float a0 = x[2 * n + 0] + ag[2 * n + 0];
    float a1 = x[2 * n + 1] + ag[2 * n + 1];
    float v = b1[c] + a0 * W1[c] + a1 * W1[HID + c];
    g_h16a[n * HID + c] = __float2half(fmaxf(v, 0.f));
}

// ---------------- layers 2/3 aggregation: one warp/node, half2 math --------
// Per-edge message computed in HFMA2; batch of 4 messages accumulated in
// half2 (independent chains), flushed to fp32 once per batch.
__device__ __forceinline__ void aggr_edge_acc(
    __half2 macc[4], const __half2 wh[7][4], const __half2 bh[4],
    uint4 ua, uint4 ub, uint4 uh)
{
    const __half2* ah = (const __half2*)&ua;   // a0..a3 (dup)
    const __half2* ah2 = (const __half2*)&ub;  // a4..a6 (dup)
    const __half2* h2 = (const __half2*)&uh;   // 8 fp16 channels
    __half2 zero = __float2half2_rn(0.f);
#pragma unroll
    for (int c = 0; c < 4; c++) {
        __half2 m = bh[c];
        m = __hfma2(ah[0], wh[0][c], m);
        m = __hfma2(ah[1], wh[1][c], m);
        m = __hfma2(ah[2], wh[2][c], m);
        m = __hfma2(ah[3], wh[3][c], m);
        m = __hfma2(ah2[0], wh[4][c], m);
        m = __hfma2(ah2[1], wh[5][c], m);
        m = __hfma2(ah2[2], wh[6][c], m);
        m = __hadd2(m, h2[c]);
        m = __hmax2(m, zero);
        macc[c] = __hadd2(macc[c], m);
    }
}

__global__ void __launch_bounds__(256)
k_aggr(int useB, const float* __restrict__ We2, const float* __restrict__ be2) {
    const __half* hin = useB ? g_h16b : g_h16a;
    int node = (blockIdx.x * blockDim.x + threadIdx.x) >> 5;
    if (node >= N_NODES) return;
    int lane = threadIdx.x & 31;
    int ch = lane * 8;

    __half2 wh[7][4];
#pragma unroll
    for (int k = 0; k < 7; k++) {
        float4 lo = *(const float4*)&We2[k * HID + ch];
        float4 hi = *(const float4*)&We2[k * HID + ch + 4];
        wh[k][0] = __floats2half2_rn(lo.x, lo.y);
        wh[k][1] = __floats2half2_rn(lo.z, lo.w);
        wh[k][2] = __floats2half2_rn(hi.x, hi.y);
        wh[k][3] = __floats2half2_rn(hi.z, hi.w);
    }
    __half2 bh[4];
    {
        float4 lo = *(const float4*)&be2[ch];
        float4 hi = *(const float4*)&be2[ch + 4];
        bh[0] = __floats2half2_rn(lo.x, lo.y);
        bh[1] = __floats2half2_rn(lo.z, lo.w);
        bh[2] = __floats2half2_rn(hi.x, hi.y);
        bh[3] = __floats2half2_rn(hi.z, hi.w);
    }

    // self term (fp32 accumulators)
    float accf[8];
    {
        uint4 uh = *(const uint4*)&hin[node * HID + ch];
        const __half2* h2 = (const __half2*)&uh;
#pragma unroll
        for (int c = 0; c < 4; c++) {
            float2 f = __half22float2(h2[c]);
            accf[2 * c + 0] = f.x;
            accf[2 * c + 1] = f.y;
        }
    }

    int beg = g_rowptr[node], end = g_rowptr[node + 1];
    int j = beg;
    for (; j + 4 <= end; j += 4) {
        int s0 = g_csrs[j], s1 = g_csrs[j + 1], s2 = g_csrs[j + 2], s3 = g_csrs[j + 3];
        uint4 a00 = g_eah[(j + 0) * 2], a01 = g_eah[(j + 0) * 2 + 1];
        uint4 a10 = g_eah[(j + 1) * 2], a11 = g_eah[(j + 1) * 2 + 1];
        uint4 a20 = g_eah[(j + 2) * 2], a21 = g_eah[(j + 2) * 2 + 1];
        uint4 a30 = g_eah[(j + 3) * 2], a31 = g_eah[(j + 3) * 2 + 1];
        uint4 h0 = *(const uint4*)&hin[s0 * HID + ch];
        uint4 h1 = *(const uint4*)&hin[s1 * HID + ch];
        uint4 h2 = *(const uint4*)&hin[s2 * HID + ch];
        uint4 h3 = *(const uint4*)&hin[s3 * HID + ch];
        __half2 macc[4];
        macc[0] = macc[1] = macc[2] = macc[3] = __float2half2_rn(0.f);
        aggr_edge_acc(macc, wh, bh, a00, a01, h0);
        aggr_edge_acc(macc, wh, bh, a10, a11, h1);
        aggr_edge_acc(macc, wh, bh, a20, a21, h2);
        aggr_edge_acc(macc, wh, bh, a30, a31, h3);
#pragma unroll
        for (int c = 0; c < 4; c++) {
            float2 f = __half22float2(macc[c]);
            accf[2 * c + 0] += f.x;
            accf[2 * c + 1] += f.y;
        }
    }
    for (; j < end; j++) {
        int s = g_csrs[j];
        uint4 a0 = g_eah[j * 2], a1 = g_eah[j * 2 + 1];
        uint4 h = *(const uint4*)&hin[s * HID + ch];
        __half2 macc[4];
        macc[0] = macc[1] = macc[2] = macc[3] = __float2half2_rn(0.f);
        aggr_edge_acc(macc, wh, bh, a0, a1, h);
#pragma unroll
        for (int c = 0; c < 4; c++) {
            float2 f = __half22float2(macc[c]);
            accf[2 * c + 0] += f.x;
            accf[2 * c + 1] += f.y;
        }
    }

    // store tf32 bits for the GEMM
    unsigned* outp = (unsigned*)g_agb + node * HID + ch;
    *(uint4*)outp =
        make_uint4(to_tf32(accf[0]), to_tf32(accf[1]), to_tf32(accf[2]), to_tf32(accf[3]));
    *(uint4*)(outp + 4) =
        make_uint4(to_tf32(accf[4]), to_tf32(accf[5]), to_tf32(accf[6]), to_tf32(accf[7]));
}

// ---------------- tf32 tensor-core GEMM ----------------
__global__ void __launch_bounds__(256)
k_gemm_tc(int layer, const float* __restrict__ b) {
    const unsigned* A = (const unsigned*)g_agb;   // tf32 bits, row-major
    __half* hout = (layer == 2) ? g_h16b : g_h16a;

    __shared__ unsigned As[8 * 4 * 4 * 32];   // [mt][ks][slot][lane]

    int tid = threadIdx.x;
    int lane = tid & 31;
    int warp = tid >> 5;
    int wr = warp >> 1;
    int wc = warp & 1;
    int rowBase = blockIdx.y * 128;
    int colBase16 = blockIdx.x * 16;

    float acc[2][8][4];
#pragma unroll
    for (int i = 0; i < 2; i++)
#pragma unroll
        for (int j = 0; j < 8; j++)
#pragma unroll
            for (int k = 0; k < 4; k++) acc[i][j][k] = 0.f;

    int a_c0 = tid & 7;
    int a_row0 = tid >> 3;
    int a_ks = a_c0 >> 1;
    int a_slot_hi = (a_c0 & 1) << 1;

    for (int kt = 0; kt < HID; kt += 32) {
#pragma unroll
        for (int i = 0; i < 4; i++) {
            int row = a_row0 + 32 * i;
            int grow = rowBase + row;
            uint4 v = make_uint4(0u, 0u, 0u, 0u);
            if (grow < N_NODES)
                v = *(const uint4*)&A[grow * HID + kt + a_c0 * 4];
            int rr = row & 15, mt = row >> 4;
            int slot = (rr >> 3) | a_slot_hi;
            *(uint4*)&As[(((mt * 4 + a_ks) * 4 + slot) * 32 + (rr & 7) * 4)] = v;
        }
        __syncthreads();

        uint2 bf[8];
#pragma unroll
        for (int ntl = 0; ntl < 8; ntl++) {
            int ct = colBase16 + wc * 8 + ntl;
            bf[ntl] = *(const uint2*)&g_W2t[((ct * 32 + (kt >> 3)) * 32 + lane) * 2];
        }
#pragma unroll
        for (int ks = 0; ks < 4; ks++) {
            uint2 bfn[8];
            if (ks < 3) {
#pragma unroll
                for (int ntl = 0; ntl < 8; ntl++) {
                    int ct = colBase16 + wc * 8 + ntl;
                    bfn[ntl] = *(const uint2*)&g_W2t[((ct * 32 + (kt >> 3) + ks + 1) * 32 + lane) * 2];
                }
            }
            unsigned af[2][4];
#pragma unroll
            for (int mtl = 0; mtl < 2; mtl++) {
                int mt = wr * 2 + mtl;
#pragma unroll
                for (int s = 0; s < 4; s++)
                    af[mtl][s] = As[((mt * 4 + ks) * 4 + s) * 32 + lane];
            }
#pragma unroll
            for (int mtl = 0; mtl < 2; mtl++)
#pragma unroll
                for (int ntl = 0; ntl < 8; ntl++) {
                    asm volatile(
                        "mma.sync.aligned.m16n8k8.row.col.f32.tf32.tf32.f32 "
                        "{%0,%1,%2,%3}, {%4,%5,%6,%7}, {%8,%9}, {%0,%1,%2,%3};"
                        : "+f"(acc[mtl][ntl][0]), "+f"(acc[mtl][ntl][1]),
                          "+f"(acc[mtl][ntl][2]), "+f"(acc[mtl][ntl][3])
                        : "r"(af[mtl][0]), "r"(af[mtl][1]),
                          "r"(af[mtl][2]), "r"(af[mtl][3]),
                          "r"(bf[ntl].x), "r"(bf[ntl].y));
                }
            if (ks < 3) {
#pragma unroll
                for (int ntl = 0; ntl < 8; ntl++) bf[ntl] = bfn[ntl];
            }
        }
        __syncthreads();
    }

    int gid = lane >> 2;
    int tig = lane & 3;
#pragma unroll
    for (int mtl = 0; mtl < 2; mtl++) {
        int row0 = rowBase + (wr * 2 + mtl) * 16 + gid;
#pragma unroll
        for (int ntl = 0; ntl < 8; ntl++) {
            int col = colBase16 * 8 + (wc * 8 + ntl) * 8 + tig * 2;
            float2 bv = *(const float2*)&b[col];
            if (row0 < N_NODES) {
                __half2 o = __floats2half2_rn(fmaxf(acc[mtl][ntl][0] + bv.x, 0.f),
                                              fmaxf(acc[mtl][ntl][1] + bv.y, 0.f));
                *(__half2*)&hout[row0 * HID + col] = o;
            }
            if (row0 + 8 < N_NODES) {
                __half2 o = __floats2half2_rn(fmaxf(acc[mtl][ntl][2] + bv.x, 0.f),
                                              fmaxf(acc[mtl][ntl][3] + bv.y, 0.f));
                *(__half2*)&hout[(row0 + 8) * HID + col] = o;
            }
        }
    }
}

// ---------------- final: sigmoid(h @ Wend + bend) ----------------
__global__ void k_final(const float* __restrict__ Wend,
                        const float* __restrict__ bend,
                        float* __restrict__ out) {
    int lane = threadIdx.x & 31;
    int warp = threadIdx.x >> 5;
    int n = blockIdx.x * 8 + warp;
    if (n >= N_NODES) return;
    float s = 0.f;
#pragma unroll
    for (int c = lane * 8; c < HID; c += 256) {
        uint4 uh = *(const uint4*)&g_h16a[n * HID + c];
        const __half2* h2 = (const __half2*)&uh;
        float4 w0 = *(const float4*)&Wend[c];
        float4 w1 = *(const float4*)&Wend[c + 4];
        float2 f0 = __half22float2(h2[0]);
        float2 f1 = __half22float2(h2[1]);
        float2 f2 = __half22float2(h2[2]);
        float2 f3 = __half22float2(h2[3]);
        s += f0.x * w0.x + f0.y * w0.y + f1.x * w0.z + f1.y * w0.w;
        s += f2.x * w1.x + f2.y * w1.y + f3.x * w1.z + f3.y * w1.w;
    }
#pragma unroll
    for (int o = 16; o; o >>= 1) s += __shfl_xor_sync(0xffffffffu, s, o);
    if (lane == 0) out[n] = 1.f / (1.f + __expf(-(s + bend[0])));
}

// ---------------- host ----------------
extern "C" void kernel_launch(void* const* d_in, const int* in_sizes, int n_in,
                              void* d_out, int out_size) {
    const float* x    = (const float*)d_in[0];
    const void*  ei   = d_in[1];
    const float* ea   = (const float*)d_in[2];
    const float* We1  = (const float*)d_in[3];
    const float* be1  = (const float*)d_in[4];
    const float* W1   = (const float*)d_in[5];
    const float* b1   = (const float*)d_in[6];
    const float* We2  = (const float*)d_in[7];
    const float* be2  = (const float*)d_in[8];
    const float* W2   = (const float*)d_in[9];
    const float* b2   = (const float*)d_in[10];
    const float* Wend = (const float*)d_in[11];
    const float* bend = (const float*)d_in[12];
    float* out = (float*)d_out;

    void *p_deg = nullptr, *p_agb = nullptr;
    cudaGetSymbolAddress(&p_deg, g_deg);
    cudaGetSymbolAddress(&p_agb, g_agb);

    k_prep<<<256, 256>>>(ei, W2);

    // CSR build (by dst)
    cudaMemsetAsync(p_deg, 0, N_NODES * sizeof(int));
    cudaMemsetAsync(p_agb, 0, N_NODES * 2 * sizeof(float));
    k_hist<<<(N_EDGES + 255) / 256, 256>>>(ei);
    k_part<<<SCAN_B, 256>>>();
    k_scanb<<<1, 256>>>();
    k_rowptr<<<SCAN_B, 256>>>();
    k_fillscat<<<(N_EDGES + 255) / 256, 256>>>(ei, ea, x, We1, be1);

    // layer 1
    k_layer1nn<<<N_NODES, 256>>>(x, W1, b1);

    // layer 2
    k_aggr<<<(N_NODES * 32 + 255) / 256, 256>>>(0, We2, be2);
    k_gemm_tc<<<dim3(2, (N_NODES + 127) / 128), 256>>>(2, b2);

    // layer 3
    k_aggr<<<(N_NODES * 32 + 255) / 256, 256>>>(1, We2, be2);
    k_gemm_tc<<<dim3(2, (N_NODES + 127) / 128), 256>>>(3, b2);

    k_final<<<(N_NODES + 7) / 8, 256>>>(Wend, bend, out);
}

// round 10
// speedup vs baseline: 1.7836x; 1.0397x over previous
#include <cuda_runtime.h>
#include <cuda_fp16.h>

#define N_NODES 50000
#define N_EDGES 1600000
#define HID 256
#define SCAN_B 196   // ceil(N_NODES/256)

// ---------------- device scratch (static, no allocs) ----------------
__device__ float4   g_agb[N_NODES*HID/4];   // aggr output (tf32 bits) / layer1 aggr (fp32)
__device__ __half   g_h16a[N_NODES*HID];    // h fp16 buffer A
__device__ __half   g_h16b[N_NODES*HID];    // h fp16 buffer B
__device__ unsigned g_W2t[65536];           // W2 in tf32 fragment order
__device__ int      g_deg[N_NODES];
__device__ int      g_rowptr[N_NODES + 1];
__device__ int      g_cur[N_NODES];
__device__ int      g_csrs[N_EDGES];        // src node, grouped by dst
__device__ uint4    g_eah[N_EDGES * 2];     // edge attrs as duplicated half2, CSR order
__device__ int      g_bsum[SCAN_B];
__device__ int      g_boff[SCAN_B];
__device__ int      g_flag;                 // 1 = edge_index int64, 0 = int32

__device__ __forceinline__ void red_add_v2(float* a, float x, float y) {
    asm volatile("red.global.add.v2.f32 [%0], {%1,%2};"
                 :: "l"(a), "f"(x), "f"(y) : "memory");
}
__device__ __forceinline__ unsigned to_tf32(float v) {
    unsigned r;
    asm("cvt.rna.tf32.f32 %0, %1;" : "=r"(r) : "f"(v));
    return r;
}
__device__ __forceinline__ int edge_src(const void* ei, int i) {
    return g_flag ? (int)((const long long*)ei)[i] : ((const int*)ei)[i];
}
__device__ __forceinline__ int edge_dst(const void* ei, int i) {
    return g_flag ? (int)((const long long*)ei)[N_EDGES + i]
                  : ((const int*)ei)[N_EDGES + i];
}

// ---------------- fused: dtype detect + W2 -> tf32 fragment table ----------
__global__ void k_prep(const void* ei, const float* __restrict__ W) {
    if (blockIdx.x == 0 && threadIdx.x == 0) {
        const long long* p = (const long long*)ei;
        int is64 = 1;
        for (int i = 0; i < 64; i++) {
            long long v = p[i];
            if (v < 0 || v >= N_NODES) { is64 = 0; break; }
        }
        g_flag = is64;
    }
    int idx = blockIdx.x * 256 + threadIdx.x;
    int slot = idx & 1;
    int l    = (idx >> 1) & 31;
    int ks   = (idx >> 6) & 31;
    int ct   = idx >> 11;
    int k = ks * 8 + (l & 3) + slot * 4;
    int n = ct * 8 + (l >> 2);
    g_W2t[idx] = to_tf32(W[k * HID + n]);
}

// ---------------- CSR build ----------------
__global__ void k_hist(const void* ei) {
    int i = blockIdx.x * blockDim.x + threadIdx.x;
    if (i < N_EDGES) atomicAdd(&g_deg[edge_dst(ei, i)], 1);
}

__global__ void k_part() {
    __shared__ int sm[256];
    int t = threadIdx.x;
    int n = blockIdx.x * 256 + t;
    int v = (n < N_NODES) ? g_deg[n] : 0;
    sm[t] = v;
    __syncthreads();
    for (int o = 128; o; o >>= 1) {
        if (t < o) sm[t] += sm[t + o];
        __syncthreads();
    }
    if (t == 0) g_bsum[blockIdx.x] = sm[0];
}

__global__ void k_scanb() {
    __shared__ int sm[256];
    int t = threadIdx.x;
    int v = (t < SCAN_B) ? g_bsum[t] : 0;
    sm[t] = v;
    __syncthreads();
    for (int o = 1; o < 256; o <<= 1) {
        int u = (t >= o) ? sm[t - o] : 0;
        __syncthreads();
        sm[t] += u;
        __syncthreads();
    }
    if (t < SCAN_B) g_boff[t] = sm[t] - v;   // exclusive
    if (t == 0) g_rowptr[N_NODES] = N_EDGES;
}

__global__ void k_rowptr() {
    __shared__ int sm[256];
    int t = threadIdx.x;
    int n = blockIdx.x * 256 + t;
    int v = (n < N_NODES) ? g_deg[n] : 0;
    sm[t] = v;
    __syncthreads();
    for (int o = 1; o < 256; o <<= 1) {
        int u = (t >= o) ? sm[t - o] : 0;
        __syncthreads();
        sm[t] += u;
        __syncthreads();
    }
    if (n < N_NODES) {
        int r = g_boff[blockIdx.x] + sm[t] - v;
        g_rowptr[n] = r;
        g_cur[n] = r;
    }
}

// ---------------- fused fill + layer1 scatter ----------------
__global__ void k_fillscat(const void* ei, const float* __restrict__ ea,
                           const float* __restrict__ x,
                           const float* __restrict__ We1,
                           const float* __restrict__ be1) {
    int e = blockIdx.x * blockDim.x + threadIdx.x;
    if (e >= N_EDGES) return;
    int s = edge_src(ei, e);
    int d = edge_dst(ei, e);
    float a[7];
    const float* ap = ea + (size_t)e * 7;
#pragma unroll
    for (int k = 0; k < 7; k++) a[k] = ap[k];

    int pos = atomicAdd(&g_cur[d], 1);
    g_csrs[pos] = s;
    uint4 v0, v1;
    __half2* p0 = (__half2*)&v0;
    __half2* p1 = (__half2*)&v1;
    p0[0] = __float2half2_rn(a[0]);
    p0[1] = __float2half2_rn(a[1]);
    p0[2] = __float2half2_rn(a[2]);
    p0[3] = __float2half2_rn(a[3]);
    p1[0] = __float2half2_rn(a[4]);
    p1[1] = __float2half2_rn(a[5]);
    p1[2] = __float2half2_rn(a[6]);
    p1[3] = __float2half2_rn(0.f);
    g_eah[pos * 2 + 0] = v0;
    g_eah[pos * 2 + 1] = v1;

    float e0 = __ldg(&be1[0]), e1 = __ldg(&be1[1]);
#pragma unroll
    for (int k = 0; k < 7; k++) {
        e0 += a[k] * __ldg(&We1[k * 2 + 0]);
        e1 += a[k] * __ldg(&We1[k * 2 + 1]);
    }
    float m0 = fmaxf(x[2 * s + 0] + e0, 0.f);
    float m1 = fmaxf(x[2 * s + 1] + e1, 0.f);
    red_add_v2(((float*)g_agb) + 2 * d, m0, m1);
}

// ---------------- layer 1 nn -> fp16 ----------------
__global__ void k_layer1nn(const float* __restrict__ x,
                           const float* __restrict__ W1,
                           const float* __restrict__ b1) {
    int n = blockIdx.x;
    int c = threadIdx.x;
    const float* ag = (const float*)g_agb;
    float a0 = x[2 * n + 0] + ag[2 * n + 0];
    float a1 = x[2 * n + 1] + ag[2 * n + 1];
    float v = b1[c] + a0 * W1[c] + a1 * W1[HID + c];
    g_h16a[n * HID + c] = __float2half(fmaxf(v, 0.f));
}

// ---------------- layers 2/3 aggregation: one warp/node, pipelined ---------
__device__ __forceinline__ void aggr_edge_acc(
    __half2 macc[4], const __half2 wh[7][4], const __half2 bh[4],
    uint4 ua, uint4 ub, uint4 uh)
{
    const __half2* ah = (const __half2*)&ua;   // a0..a3 (dup)
    const __half2* ah2 = (const __half2*)&ub;  // a4..a6 (dup)
    const __half2* h2 = (const __half2*)&uh;   // 8 fp16 channels
    __half2 zero = __float2half2_rn(0.f);
#pragma unroll
    for (int c = 0; c < 4; c++) {
        __half2 m = bh[c];
        m = __hfma2(ah[0], wh[0][c], m);
        m = __hfma2(ah[1], wh[1][c], m);
        m = __hfma2(ah[2], wh[2][c], m);
        m = __hfma2(ah[3], wh[3][c], m);
        m = __hfma2(ah2[0], wh[4][c], m);
        m = __hfma2(ah2[1], wh[5][c], m);
        m = __hfma2(ah2[2], wh[6][c], m);
        m = __hadd2(m, h2[c]);
        m = __hmax2(m, zero);
        macc[c] = __hadd2(macc[c], m);
    }
}

__device__ __forceinline__ void flush_macc(float* accf, const __half2 macc[4]) {
#pragma unroll
    for (int c = 0; c < 4; c++) {
        float2 f = __half22float2(macc[c]);
        accf[2 * c + 0] += f.x;
        accf[2 * c + 1] += f.y;
    }
}

__global__ void __launch_bounds__(256, 2)
k_aggr(int useB, const float* __restrict__ We2, const float* __restrict__ be2) {
    const __half* hin = useB ? g_h16b : g_h16a;
    int node = (blockIdx.x * blockDim.x + threadIdx.x) >> 5;
    if (node >= N_NODES) return;
    int lane = threadIdx.x & 31;
    int ch = lane * 8;

    __half2 wh[7][4];
#pragma unroll
    for (int k = 0; k < 7; k++) {
        float4 lo = *(const float4*)&We2[k * HID + ch];
        float4 hi = *(const float4*)&We2[k * HID + ch + 4];
        wh[k][0] = __floats2half2_rn(lo.x, lo.y);
        wh[k][1] = __floats2half2_rn(lo.z, lo.w);
        wh[k][2] = __floats2half2_rn(hi.x, hi.y);
        wh[k][3] = __floats2half2_rn(hi.z, hi.w);
    }
    __half2 bh[4];
    {
        float4 lo = *(const float4*)&be2[ch];
        float4 hi = *(const float4*)&be2[ch + 4];
        bh[0] = __floats2half2_rn(lo.x, lo.y);
        bh[1] = __floats2half2_rn(lo.z, lo.w);
        bh[2] = __floats2half2_rn(hi.x, hi.y);
        bh[3] = __floats2half2_rn(hi.z, hi.w);
    }

    float accf[8];
    {
        uint4 uh = *(const uint4*)&hin[node * HID + ch];
        const __half2* h2 = (const __half2*)&uh;
#pragma unroll
        for (int c = 0; c < 4; c++) {
            float2 f = __half22float2(h2[c]);
            accf[2 * c + 0] = f.x;
            accf[2 * c + 1] = f.y;
        }
    }

    int beg = g_rowptr[node], end = g_rowptr[node + 1];
    int j = beg;

    // ---- 8-edge batches: all 8 scattered h-gathers issued up front ----
    for (; j + 8 <= end; j += 8) {
        int s0 = g_csrs[j + 0], s1 = g_csrs[j + 1];
        int s2 = g_csrs[j + 2], s3 = g_csrs[j + 3];
        int s4 = g_csrs[j + 4], s5 = g_csrs[j + 5];
        int s6 = g_csrs[j + 6], s7 = g_csrs[j + 7];
        uint4 h0 = *(const uint4*)&hin[s0 * HID + ch];
        uint4 h1 = *(const uint4*)&hin[s1 * HID + ch];
        uint4 h2 = *(const uint4*)&hin[s2 * HID + ch];
        uint4 h3 = *(const uint4*)&hin[s3 * HID + ch];
        uint4 h4 = *(const uint4*)&hin[s4 * HID + ch];
        uint4 h5 = *(const uint4*)&hin[s5 * HID + ch];
        uint4 h6 = *(const uint4*)&hin[s6 * HID + ch];
        uint4 h7 = *(const uint4*)&hin[s7 * HID + ch];

        // attrs for edges 0-3, compute while h4-7 are still in flight
        {
            uint4 a0 = g_eah[(j + 0) * 2], b0 = g_eah[(j + 0) * 2 + 1];
            uint4 a1 = g_eah[(j + 1) * 2], b1 = g_eah[(j + 1) * 2 + 1];
            uint4 a2 = g_eah[(j + 2) * 2], b2 = g_eah[(j + 2) * 2 + 1];
            uint4 a3 = g_eah[(j + 3) * 2], b3 = g_eah[(j + 3) * 2 + 1];
            __half2 macc[4];
            macc[0] = macc[1] = macc[2] = macc[3] = __float2half2_rn(0.f);
            aggr_edge_acc(macc, wh, bh, a0, b0, h0);
            aggr_edge_acc(macc, wh, bh, a1, b1, h1);
            aggr_edge_acc(macc, wh, bh, a2, b2, h2);
            aggr_edge_acc(macc, wh, bh, a3, b3, h3);
            flush_macc(accf, macc);
        }
        {
            uint4 a4 = g_eah[(j + 4) * 2], b4 = g_eah[(j + 4) * 2 + 1];
            uint4 a5 = g_eah[(j + 5) * 2], b5 = g_eah[(j + 5) * 2 + 1];
            uint4 a6 = g_eah[(j + 6) * 2], b6 = g_eah[(j + 6) * 2 + 1];
            uint4 a7 = g_eah[(j + 7) * 2], b7 = g_eah[(j + 7) * 2 + 1];
            __half2 macc[4];
            macc[0] = macc[1] = macc[2] = macc[3] = __float2half2_rn(0.f);
            aggr_edge_acc(macc, wh, bh, a4, b4, h4);
            aggr_edge_acc(macc, wh, bh, a5, b5, h5);
            aggr_edge_acc(macc, wh, bh, a6, b6, h6);
            aggr_edge_acc(macc, wh, bh, a7, b7, h7);
            flush_macc(accf, macc);
        }
    }

    // ---- 4-edge batch ----
    for (; j + 4 <= end; j += 4) {
        int s0 = g_csrs[j + 0], s1 = g_csrs[j + 1];
        int s2 = g_csrs[j + 2], s3 = g_csrs[j + 3];
        uint4 h0 = *(const uint4*)&hin[s0 * HID + ch];
        uint4 h1 = *(const uint4*)&hin[s1 * HID + ch];
        uint4 h2 = *(const uint4*)&hin[s2 * HID + ch];
        uint4 h3 = *(const uint4*)&hin[s3 * HID + ch];
        uint4 a0 = g_eah[(j + 0) * 2], b0 = g_eah[(j + 0) * 2 + 1];
        uint4 a1 = g_eah[(j + 1) * 2], b1 = g_eah[(j + 1) * 2 + 1];
        uint4 a2 = g_eah[(j + 2) * 2], b2 = g_eah[(j + 2) * 2 + 1];
        uint4 a3 = g_eah[(j + 3) * 2], b3 = g_eah[(j + 3) * 2 + 1];
        __half2 macc[4];
        macc[0] = macc[1] = macc[2] = macc[3] = __float2half2_rn(0.f);
        aggr_edge_acc(macc, wh, bh, a0, b0, h0);
        aggr_edge_acc(macc, wh, bh, a1, b1, h1);
        aggr_edge_acc(macc, wh, bh, a2, b2, h2);
        aggr_edge_acc(macc, wh, bh, a3, b3, h3);
        flush_macc(accf, macc);
    }

    // ---- scalar tail ----
    for (; j < end; j++) {
        int s = g_csrs[j];
        uint4 a0 = g_eah[j * 2], a1 = g_eah[j * 2 + 1];
        uint4 h = *(const uint4*)&hin[s * HID + ch];
        __half2 macc[4];
        macc[0] = macc[1] = macc[2] = macc[3] = __float2half2_rn(0.f);
        aggr_edge_acc(macc, wh, bh, a0, a1, h);
        flush_macc(accf, macc);
    }

    unsigned* outp = (unsigned*)g_agb + node * HID + ch;
    *(uint4*)outp =
        make_uint4(to_tf32(accf[0]), to_tf32(accf[1]), to_tf32(accf[2]), to_tf32(accf[3]));
    *(uint4*)(outp + 4) =
        make_uint4(to_tf32(accf[4]), to_tf32(accf[5]), to_tf32(accf[6]), to_tf32(accf[7]));
}

// ---------------- tf32 tensor-core GEMM ----------------
__global__ void __launch_bounds__(256)
k_gemm_tc(int layer, const float* __restrict__ b) {
    const unsigned* A = (const unsigned*)g_agb;   // tf32 bits, row-major
    __half* hout = (layer == 2) ? g_h16b : g_h16a;

    __shared__ unsigned As[8 * 4 * 4 * 32];   // [mt][ks][slot][lane]

    int tid = threadIdx.x;
    int lane = tid & 31;
    int warp = tid >> 5;
    int wr = warp >> 1;
    int wc = warp & 1;
    int rowBase = blockIdx.y * 128;
    int colBase16 = blockIdx.x * 16;

    float acc[2][8][4];
#pragma unroll
    for (int i = 0; i < 2; i++)
#pragma unroll
        for (int j = 0; j < 8; j++)
#pragma unroll
            for (int k = 0; k < 4; k++) acc[i][j][k] = 0.f;

    int a_c0 = tid & 7;
    int a_row0 = tid >> 3;
    int a_ks = a_c0 >> 1;
    int a_slot_hi = (a_c0 & 1) << 1;

    for (int kt = 0; kt < HID; kt += 32) {
#pragma unroll
        for (int i = 0; i < 4; i++) {
            int row = a_row0 + 32 * i;
            int grow = rowBase + row;
            uint4 v = make_uint4(0u, 0u, 0u, 0u);
            if (grow < N_NODES)
                v = *(const uint4*)&A[grow * HID + kt + a_c0 * 4];
            int rr = row & 15, mt = row >> 4;
            int slot = (rr >> 3) | a_slot_hi;
            *(uint4*)&As[(((mt * 4 + a_ks) * 4 + slot) * 32 + (rr & 7) * 4)] = v;
        }
        __syncthreads();

        uint2 bf[8];
#pragma unroll
        for (int ntl = 0; ntl < 8; ntl++) {
            int ct = colBase16 + wc * 8 + ntl;
            bf[ntl] = *(const uint2*)&g_W2t[((ct * 32 + (kt >> 3)) * 32 + lane) * 2];
        }
#pragma unroll
        for (int ks = 0; ks < 4; ks++) {
            uint2 bfn[8];
            if (ks < 3) {
#pragma unroll
                for (int ntl = 0; ntl < 8; ntl++) {
                    int ct = colBase16 + wc * 8 + ntl;
                    bfn[ntl] = *(const uint2*)&g_W2t[((ct * 32 + (kt >> 3) + ks + 1) * 32 + lane) * 2];
                }
            }
            unsigned af[2][4];
#pragma unroll
            for (int mtl = 0; mtl < 2; mtl++) {
                int mt = wr * 2 + mtl;
#pragma unroll
                for (int s = 0; s < 4; s++)
                    af[mtl][s] = As[((mt * 4 + ks) * 4 + s) * 32 + lane];
            }
#pragma unroll
            for (int mtl = 0; mtl < 2; mtl++)
#pragma unroll
                for (int ntl = 0; ntl < 8; ntl++) {
                    asm volatile(
                        "mma.sync.aligned.m16n8k8.row.col.f32.tf32.tf32.f32 "
                        "{%0,%1,%2,%3}, {%4,%5,%6,%7}, {%8,%9}, {%0,%1,%2,%3};"
                        : "+f"(acc[mtl][ntl][0]), "+f"(acc[mtl][ntl][1]),
                          "+f"(acc[mtl][ntl][2]), "+f"(acc[mtl][ntl][3])
                        : "r"(af[mtl][0]), "r"(af[mtl][1]),
                          "r"(af[mtl][2]), "r"(af[mtl][3]),
                          "r"(bf[ntl].x), "r"(bf[ntl].y));
                }
            if (ks < 3) {
#pragma unroll
                for (int ntl = 0; ntl < 8; ntl++) bf[ntl] = bfn[ntl];
            }
        }
        __syncthreads();
    }

    int gid = lane >> 2;
    int tig = lane & 3;
#pragma unroll
    for (int mtl = 0; mtl < 2; mtl++) {
        int row0 = rowBase + (wr * 2 + mtl) * 16 + gid;
#pragma unroll
        for (int ntl = 0; ntl < 8; ntl++) {
            int col = colBase16 * 8 + (wc * 8 + ntl) * 8 + tig * 2;
            float2 bv = *(const float2*)&b[col];
            if (row0 < N_NODES) {
                __half2 o = __floats2half2_rn(fmaxf(acc[mtl][ntl][0] + bv.x, 0.f),
                                              fmaxf(acc[mtl][ntl][1] + bv.y, 0.f));
                *(__half2*)&hout[row0 * HID + col] = o;
            }
            if (row0 + 8 < N_NODES) {
                __half2 o = __floats2half2_rn(fmaxf(acc[mtl][ntl][2] + bv.x, 0.f),
                                              fmaxf(acc[mtl][ntl][3] + bv.y, 0.f));
                *(__half2*)&hout[(row0 + 8) * HID + col] = o;
            }
        }
    }
}

// ---------------- final: sigmoid(h @ Wend + bend) ----------------
__global__ void k_final(const float* __restrict__ Wend,
                        const float* __restrict__ bend,
                        float* __restrict__ out) {
    int lane = threadIdx.x & 31;
    int warp = threadIdx.x >> 5;
    int n = blockIdx.x * 8 + warp;
    if (n >= N_NODES) return;
    float s = 0.f;
#pragma unroll
    for (int c = lane * 8; c < HID; c += 256) {
        uint4 uh = *(const uint4*)&g_h16a[n * HID + c];
        const __half2* h2 = (const __half2*)&uh;
        float4 w0 = *(const float4*)&Wend[c];
        float4 w1 = *(const float4*)&Wend[c + 4];
        float2 f0 = __half22float2(h2[0]);
        float2 f1 = __half22float2(h2[1]);
        float2 f2 = __half22float2(h2[2]);
        float2 f3 = __half22float2(h2[3]);
        s += f0.x * w0.x + f0.y * w0.y + f1.x * w0.z + f1.y * w0.w;
        s += f2.x * w1.x + f2.y * w1.y + f3.x * w1.z + f3.y * w1.w;
    }
#pragma unroll
    for (int o = 16; o; o >>= 1) s += __shfl_xor_sync(0xffffffffu, s, o);
    if (lane == 0) out[n] = 1.f / (1.f + __expf(-(s + bend[0])));
}

// ---------------- host ----------------
extern "C" void kernel_launch(void* const* d_in, const int* in_sizes, int n_in,
                              void* d_out, int out_size) {
    const float* x    = (const float*)d_in[0];
    const void*  ei   = d_in[1];
    const float* ea   = (const float*)d_in[2];
    const float* We1  = (const float*)d_in[3];
    const float* be1  = (const float*)d_in[4];
    const float* W1   = (const float*)d_in[5];
    const float* b1   = (const float*)d_in[6];
    const float* We2  = (const float*)d_in[7];
    const float* be2  = (const float*)d_in[8];
    const float* W2   = (const float*)d_in[9];
    const float* b2   = (const float*)d_in[10];
    const float* Wend = (const float*)d_in[11];
    const float* bend = (const float*)d_in[12];
    float* out = (float*)d_out;

    void *p_deg = nullptr, *p_agb = nullptr;
    cudaGetSymbolAddress(&p_deg, g_deg);
    cudaGetSymbolAddress(&p_agb, g_agb);

    k_prep<<<256, 256>>>(ei, W2);

    // CSR build (by dst)
    cudaMemsetAsync(p_deg, 0, N_NODES * sizeof(int));
    cudaMemsetAsync(p_agb, 0, N_NODES * 2 * sizeof(float));
    k_hist<<<(N_EDGES + 255) / 256, 256>>>(ei);
    k_part<<<SCAN_B, 256>>>();
    k_scanb<<<1, 256>>>();
    k_rowptr<<<SCAN_B, 256>>>();
    k_fillscat<<<(N_EDGES + 255) / 256, 256>>>(ei, ea, x, We1, be1);

    // layer 1
    k_layer1nn<<<N_NODES, 256>>>(x, W1, b1);

    // layer 2
    k_aggr<<<(N_NODES * 32 + 255) / 256, 256>>>(0, We2, be2);
    k_gemm_tc<<<dim3(2, (N_NODES + 127) / 128), 256>>>(2, b2);

    // layer 3
    k_aggr<<<(N_NODES * 32 + 255) / 256, 256>>>(1, We2, be2);
    k_gemm_tc<<<dim3(2, (N_NODES + 127) / 128), 256>>>(3, b2);

    k_final<<<(N_NODES + 7) / 8, 256>>>(Wend, bend, out);
}

// round 11
// speedup vs baseline: 1.9975x; 1.1199x over previous
#include <cuda_runtime.h>
#include <cuda_fp16.h>

#define N_NODES 50000
#define N_EDGES 1600000
#define HID 256
#define SCAN_B 196   // ceil(N_NODES/256)

// ---------------- device scratch (static, no allocs) ----------------
__device__ float4   g_agb[N_NODES*HID/4];   // aggr output (tf32 bits) / layer1 aggr (fp32)
__device__ __half   g_h16a[N_NODES*HID];    // h fp16 buffer A
__device__ __half   g_h16b[N_NODES*HID];    // h fp16 buffer B
__device__ unsigned g_W2t[65536];           // W2 in tf32 fragment order
__device__ int      g_deg[N_NODES];
__device__ int      g_rowptr[N_NODES + 1];
__device__ int      g_cur[N_NODES];
__device__ int      g_csrs[N_EDGES];        // src node, grouped by dst
__device__ uint4    g_eah[N_EDGES];         // edge attrs: 8 packed halfs, CSR order
__device__ unsigned long long g_scanst[SCAN_B];  // decoupled-lookback state
__device__ int      g_flag;                 // 1 = edge_index int64, 0 = int32

__device__ __forceinline__ void red_add_v2(float* a, float x, float y) {
    asm volatile("red.global.add.v2.f32 [%0], {%1,%2};"
                 :: "l"(a), "f"(x), "f"(y) : "memory");
}
__device__ __forceinline__ unsigned to_tf32(float v) {
    unsigned r;
    asm("cvt.rna.tf32.f32 %0, %1;" : "=r"(r) : "f"(v));
    return r;
}
__device__ __forceinline__ int edge_src(const void* ei, int i) {
    return g_flag ? (int)((const long long*)ei)[i] : ((const int*)ei)[i];
}
__device__ __forceinline__ int edge_dst(const void* ei, int i) {
    return g_flag ? (int)((const long long*)ei)[N_EDGES + i]
                  : ((const int*)ei)[N_EDGES + i];
}

// ------- fused prep: detect dtype, W2->tf32 frags, zero deg/agb/scan -------
__global__ void k_prep(const void* ei, const float* __restrict__ W) {
    int idx = blockIdx.x * 256 + threadIdx.x;   // 65536 threads
    if (idx == 0) {
        const long long* p = (const long long*)ei;
        int is64 = 1;
        for (int i = 0; i < 64; i++) {
            long long v = p[i];
            if (v < 0 || v >= N_NODES) { is64 = 0; break; }
        }
        g_flag = is64;
    }
    {   // W2 fragment table
        int slot = idx & 1;
        int l    = (idx >> 1) & 31;
        int ks   = (idx >> 6) & 31;
        int ct   = idx >> 11;
        int k = ks * 8 + (l & 3) + slot * 4;
        int n = ct * 8 + (l >> 2);
        g_W2t[idx] = to_tf32(W[k * HID + n]);
    }
    if (idx < N_NODES) g_deg[idx] = 0;
    if (idx < SCAN_B)  g_scanst[idx] = 0ULL;
    float* ag = (float*)g_agb;
    for (int i = idx; i < 2 * N_NODES; i += 65536) ag[i] = 0.f;
}

// ---------------- CSR build ----------------
__global__ void k_hist(const void* ei) {
    int i = blockIdx.x * blockDim.x + threadIdx.x;
    if (i < N_EDGES) atomicAdd(&g_deg[edge_dst(ei, i)], 1);
}

// single-pass scan via decoupled lookback: deg -> rowptr, cur
__global__ void k_scan1() {
    __shared__ int sm[256];
    __shared__ int s_prefix;
    int t = threadIdx.x;
    int bid = blockIdx.x;
    int n = bid * 256 + t;
    int v = (n < N_NODES) ? g_deg[n] : 0;
    sm[t] = v;
    __syncthreads();
    for (int o = 1; o < 256; o <<= 1) {
        int u = (t >= o) ? sm[t - o] : 0;
        __syncthreads();
        sm[t] += u;
        __syncthreads();
    }
    int total = sm[255];
    if (t == 0) {
        unsigned long long st;
        if (bid == 0) {
            st = (2ULL << 32) | (unsigned)total;
            atomicExch(&g_scanst[0], st);
            s_prefix = 0;
        } else {
            st = (1ULL << 32) | (unsigned)total;
            atomicExch(&g_scanst[bid], st);
            int pref = 0;
            int p = bid - 1;
            while (true) {
                unsigned long long s2;
                do { s2 = atomicAdd(&g_scanst[p], 0ULL); } while ((s2 >> 32) == 0ULL);
                pref += (int)(unsigned)s2;
                if ((s2 >> 32) == 2ULL) break;
                p--;
            }
            atomicExch(&g_scanst[bid], (2ULL << 32) | (unsigned)(total + pref));
            s_prefix = pref;
        }
    }
    __syncthreads();
    int ex = s_prefix + sm[t] - v;   // exclusive prefix
    if (n < N_NODES) {
        g_rowptr[n] = ex;
        g_cur[n] = ex;
    }
    if (bid == SCAN_B - 1 && t == 255) g_rowptr[N_NODES] = N_EDGES;
}

// ---------------- fused fill + layer1 scatter ----------------
__global__ void k_fillscat(const void* ei, const float* __restrict__ ea,
                           const float* __restrict__ x,
                           const float* __restrict__ We1,
                           const float* __restrict__ be1) {
    int e = blockIdx.x * blockDim.x + threadIdx.x;
    if (e >= N_EDGES) return;
    int s = edge_src(ei, e);
    int d = edge_dst(ei, e);
    float a[7];
    const float* ap = ea + (size_t)e * 7;
#pragma unroll
    for (int k = 0; k < 7; k++) a[k] = ap[k];

    int pos = atomicAdd(&g_cur[d], 1);
    g_csrs[pos] = s;
    uint4 v;
    __half2* p = (__half2*)&v;
    p[0] = __floats2half2_rn(a[0], a[1]);
    p[1] = __floats2half2_rn(a[2], a[3]);
    p[2] = __floats2half2_rn(a[4], a[5]);
    p[3] = __floats2half2_rn(a[6], 0.f);
    g_eah[pos] = v;

    float e0 = __ldg(&be1[0]), e1 = __ldg(&be1[1]);
#pragma unroll
    for (int k = 0; k < 7; k++) {
        e0 += a[k] * __ldg(&We1[k * 2 + 0]);
        e1 += a[k] * __ldg(&We1[k * 2 + 1]);
    }
    float m0 = fmaxf(x[2 * s + 0] + e0, 0.f);
    float m1 = fmaxf(x[2 * s + 1] + e1, 0.f);
    red_add_v2(((float*)g_agb) + 2 * d, m0, m1);
}

// ---------------- layer 1 nn -> fp16 ----------------
__global__ void k_layer1nn(const float* __restrict__ x,
                           const float* __restrict__ W1,
                           const float* __restrict__ b1) {
    int n = blockIdx.x;
    int c = threadIdx.x;
    const float* ag = (const float*)g_agb;
    float a0 = x[2 * n + 0] + ag[2 * n + 0];
    float a1 = x[2 * n + 1] + ag[2 * n + 1];
    float v = b1[c] + a0 * W1[c] + a1 * W1[HID + c];
    g_h16a[n * HID + c] = __float2half(fmaxf(v, 0.f));
}

// ---------------- layers 2/3 aggregation ----------------
// One warp/node, 8 ch/lane. Per-edge message in HFMA2 with packed attrs
// (split in-register). 8-edge batches; src ids software-pipelined one
// batch ahead so h-gathers issue immediately at batch top.
__device__ __forceinline__ void aggr_edge_acc(
    __half2 macc[4], const __half2 wh[7][4], const __half2 bh[4],
    uint4 ua, uint4 uh)
{
    const __half2* ap = (const __half2*)&ua;   // (a0,a1)(a2,a3)(a4,a5)(a6,_)
    __half2 a0 = __low2half2(ap[0]),  a1 = __high2half2(ap[0]);
    __half2 a2 = __low2half2(ap[1]),  a3 = __high2half2(ap[1]);
    __half2 a4 = __low2half2(ap[2]),  a5 = __high2half2(ap[2]);
    __half2 a6 = __low2half2(ap[3]);
    const __half2* h2 = (const __half2*)&uh;   // 8 fp16 channels
    __half2 zero = __float2half2_rn(0.f);
#pragma unroll
    for (int c = 0; c < 4; c++) {
        __half2 m = bh[c];
        m = __hfma2(a0, wh[0][c], m);
        m = __hfma2(a1, wh[1][c], m);
        m = __hfma2(a2, wh[2][c], m);
        m = __hfma2(a3, wh[3][c], m);
        m = __hfma2(a4, wh[4][c], m);
        m = __hfma2(a5, wh[5][c], m);
        m = __hfma2(a6, wh[6][c], m);
        m = __hadd2(m, h2[c]);
        m = __hmax2(m, zero);
        macc[c] = __hadd2(macc[c], m);
    }
}

__device__ __forceinline__ void flush_macc(float* accf, const __half2 macc[4]) {
#pragma unroll
    for (int c = 0; c < 4; c++) {
        float2 f = __half22float2(macc[c]);
        accf[2 * c + 0] += f.x;
        accf[2 * c + 1] += f.y;
    }
}

__global__ void __launch_bounds__(256, 2)
k_aggr(int useB, const float* __restrict__ We2, const float* __restrict__ be2) {
    const __half* hin = useB ? g_h16b : g_h16a;
    int node = (blockIdx.x * blockDim.x + threadIdx.x) >> 5;
    if (node >= N_NODES) return;
    int lane = threadIdx.x & 31;
    int ch = lane * 8;

    __half2 wh[7][4];
#pragma unroll
    for (int k = 0; k < 7; k++) {
        float4 lo = *(const float4*)&We2[k * HID + ch];
        float4 hi = *(const float4*)&We2[k * HID + ch + 4];
        wh[k][0] = __floats2half2_rn(lo.x, lo.y);
        wh[k][1] = __floats2half2_rn(lo.z, lo.w);
        wh[k][2] = __floats2half2_rn(hi.x, hi.y);
        wh[k][3] = __floats2half2_rn(hi.z, hi.w);
    }
    __half2 bh[4];
    {
        float4 lo = *(const float4*)&be2[ch];
        float4 hi = *(const float4*)&be2[ch + 4];
        bh[0] = __floats2half2_rn(lo.x, lo.y);
        bh[1] = __floats2half2_rn(lo.z, lo.w);
        bh[2] = __floats2half2_rn(hi.x, hi.y);
        bh[3] = __floats2half2_rn(hi.z, hi.w);
    }

    float accf[8];
    {
        uint4 uh = *(const uint4*)&hin[node * HID + ch];
        const __half2* h2 = (const __half2*)&uh;
#pragma unroll
        for (int c = 0; c < 4; c++) {
            float2 f = __half22float2(h2[c]);
            accf[2 * c + 0] = f.x;
            accf[2 * c + 1] = f.y;
        }
    }

    int beg = g_rowptr[node], end = g_rowptr[node + 1];
    int j = beg;

    int s[8];
    if (j + 8 <= end) {
#pragma unroll
        for (int i = 0; i < 8; i++) s[i] = g_csrs[j + i];
    }

    for (; j + 8 <= end; j += 8) {
        // h-gathers issue immediately (src ids already in registers)
        uint4 h0 = *(const uint4*)&hin[s[0] * HID + ch];
        uint4 h1 = *(const uint4*)&hin[s[1] * HID + ch];
        uint4 h2 = *(const uint4*)&hin[s[2] * HID + ch];
        uint4 h3 = *(const uint4*)&hin[s[3] * HID + ch];
        uint4 h4 = *(const uint4*)&hin[s[4] * HID + ch];
        uint4 h5 = *(const uint4*)&hin[s[5] * HID + ch];
        uint4 h6 = *(const uint4*)&hin[s[6] * HID + ch];
        uint4 h7 = *(const uint4*)&hin[s[7] * HID + ch];

        // prefetch next batch's src ids during compute
        bool more = (j + 16 <= end);
        int sn[8];
        if (more) {
#pragma unroll
            for (int i = 0; i < 8; i++) sn[i] = g_csrs[j + 8 + i];
        }

        {
            uint4 a0 = g_eah[j + 0], a1 = g_eah[j + 1];
            uint4 a2 = g_eah[j + 2], a3 = g_eah[j + 3];
            __half2 macc[4];
            macc[0] = macc[1] = macc[2] = macc[3] = __float2half2_rn(0.f);
            aggr_edge_acc(macc, wh, bh, a0, h0);
            aggr_edge_acc(macc, wh, bh, a1, h1);
            aggr_edge_acc(macc, wh, bh, a2, h2);
            aggr_edge_acc(macc, wh, bh, a3, h3);
            flush_macc(accf, macc);
        }
        {
            uint4 a4 = g_eah[j + 4], a5 = g_eah[j + 5];
            uint4 a6 = g_eah[j + 6], a7 = g_eah[j + 7];
            __half2 macc[4];
            macc[0] = macc[1] = macc[2] = macc[3] = __float2half2_rn(0.f);
            aggr_edge_acc(macc, wh, bh, a4, h4);
            aggr_edge_acc(macc, wh, bh, a5, h5);
            aggr_edge_acc(macc, wh, bh, a6, h6);
            aggr_edge_acc(macc, wh, bh, a7, h7);
            flush_macc(accf, macc);
        }
        if (more) {
#pragma unroll
            for (int i = 0; i < 8; i++) s[i] = sn[i];
        }
    }

    // tail (<8 edges)
    for (; j < end; j++) {
        int sj = g_csrs[j];
        uint4 a = g_eah[j];
        uint4 h = *(const uint4*)&hin[sj * HID + ch];
        __half2 macc[4];
        macc[0] = macc[1] = macc[2] = macc[3] = __float2half2_rn(0.f);
        aggr_edge_acc(macc, wh, bh, a, h);
        flush_macc(accf, macc);
    }

    unsigned* outp = (unsigned*)g_agb + node * HID + ch;
    *(uint4*)outp =
        make_uint4(to_tf32(accf[0]), to_tf32(accf[1]), to_tf32(accf[2]), to_tf32(accf[3]));
    *(uint4*)(outp + 4) =
        make_uint4(to_tf32(accf[4]), to_tf32(accf[5]), to_tf32(accf[6]), to_tf32(accf[7]));
}

// ---------------- tf32 tensor-core GEMM ----------------
__global__ void __launch_bounds__(256)
k_gemm_tc(int layer, const float* __restrict__ b) {
    const unsigned* A = (const unsigned*)g_agb;   // tf32 bits, row-major
    __half* hout = (layer == 2) ? g_h16b : g_h16a;

    __shared__ unsigned As[8 * 4 * 4 * 32];   // [mt][ks][slot][lane]

    int tid = threadIdx.x;
    int lane = tid & 31;
    int warp = tid >> 5;
    int wr = warp >> 1;
    int wc = warp & 1;
    int rowBase = blockIdx.y * 128;
    int colBase16 = blockIdx.x * 16;

    float acc[2][8][4];
#pragma unroll
    for (int i = 0; i < 2; i++)
#pragma unroll
        for (int j = 0; j < 8; j++)
#pragma unroll
            for (int k = 0; k < 4; k++) acc[i][j][k] = 0.f;

    int a_c0 = tid & 7;
    int a_row0 = tid >> 3;
    int a_ks = a_c0 >> 1;
    int a_slot_hi = (a_c0 & 1) << 1;

    for (int kt = 0; kt < HID; kt += 32) {
#pragma unroll
        for (int i = 0; i < 4; i++) {
            int row = a_row0 + 32 * i;
            int grow = rowBase + row;
            uint4 v = make_uint4(0u, 0u, 0u, 0u);
            if (grow < N_NODES)
                v = *(const uint4*)&A[grow * HID + kt + a_c0 * 4];
            int rr = row & 15, mt = row >> 4;
            int slot = (rr >> 3) | a_slot_hi;
            *(uint4*)&As[(((mt * 4 + a_ks) * 4 + slot) * 32 + (rr & 7) * 4)] = v;
        }
        __syncthreads();

        uint2 bf[8];
#pragma unroll
        for (int ntl = 0; ntl < 8; ntl++) {
            int ct = colBase16 + wc * 8 + ntl;
            bf[ntl] = *(const uint2*)&g_W2t[((ct * 32 + (kt >> 3)) * 32 + lane) * 2];
        }
#pragma unroll
        for (int ks = 0; ks < 4; ks++) {
            uint2 bfn[8];
            if (ks < 3) {
#pragma unroll
                for (int ntl = 0; ntl < 8; ntl++) {
                    int ct = colBase16 + wc * 8 + ntl;
                    bfn[ntl] = *(const uint2*)&g_W2t[((ct * 32 + (kt >> 3) + ks + 1) * 32 + lane) * 2];
                }
            }
            unsigned af[2][4];
#pragma unroll
            for (int mtl = 0; mtl < 2; mtl++) {
                int mt = wr * 2 + mtl;
#pragma unroll
                for (int s = 0; s < 4; s++)
                    af[mtl][s] = As[((mt * 4 + ks) * 4 + s) * 32 + lane];
            }
#pragma unroll
            for (int mtl = 0; mtl < 2; mtl++)
#pragma unroll
                for (int ntl = 0; ntl < 8; ntl++) {
                    asm volatile(
                        "mma.sync.aligned.m16n8k8.row.col.f32.tf32.tf32.f32 "
                        "{%0,%1,%2,%3}, {%4,%5,%6,%7}, {%8,%9}, {%0,%1,%2,%3};"
                        : "+f"(acc[mtl][ntl][0]), "+f"(acc[mtl][ntl][1]),
                          "+f"(acc[mtl][ntl][2]), "+f"(acc[mtl][ntl][3])
                        : "r"(af[mtl][0]), "r"(af[mtl][1]),
                          "r"(af[mtl][2]), "r"(af[mtl][3]),
                          "r"(bf[ntl].x), "r"(bf[ntl].y));
                }
            if (ks < 3) {
#pragma unroll
                for (int ntl = 0; ntl < 8; ntl++) bf[ntl] = bfn[ntl];
            }
        }
        __syncthreads();
    }

    int gid = lane >> 2;
    int tig = lane & 3;
#pragma unroll
    for (int mtl = 0; mtl < 2; mtl++) {
        int row0 = rowBase + (wr * 2 + mtl) * 16 + gid;
#pragma unroll
        for (int ntl = 0; ntl < 8; ntl++) {
            int col = colBase16 * 8 + (wc * 8 + ntl) * 8 + tig * 2;
            float2 bv = *(const float2*)&b[col];
            if (row0 < N_NODES) {
                __half2 o = __floats2half2_rn(fmaxf(acc[mtl][ntl][0] + bv.x, 0.f),
                                              fmaxf(acc[mtl][ntl][1] + bv.y, 0.f));
                *(__half2*)&hout[row0 * HID + col] = o;
            }
            if (row0 + 8 < N_NODES) {
                __half2 o = __floats2half2_rn(fmaxf(acc[mtl][ntl][2] + bv.x, 0.f),
                                              fmaxf(acc[mtl][ntl][3] + bv.y, 0.f));
                *(__half2*)&hout[(row0 + 8) * HID + col] = o;
            }
        }
    }
}

// ---------------- final: sigmoid(h @ Wend + bend) ----------------
__global__ void k_final(const float* __restrict__ Wend,
                        const float* __restrict__ bend,
                        float* __restrict__ out) {
    int lane = threadIdx.x & 31;
    int warp = threadIdx.x >> 5;
    int n = blockIdx.x * 8 + warp;
    if (n >= N_NODES) return;
    float s = 0.f;
#pragma unroll
    for (int c = lane * 8; c < HID; c += 256) {
        uint4 uh = *(const uint4*)&g_h16a[n * HID + c];
        const __half2* h2 = (const __half2*)&uh;
        float4 w0 = *(const float4*)&Wend[c];
        float4 w1 = *(const float4*)&Wend[c + 4];
        float2 f0 = __half22float2(h2[0]);
        float2 f1 = __half22float2(h2[1]);
        float2 f2 = __half22float2(h2[2]);
        float2 f3 = __half22float2(h2[3]);
        s += f0.x * w0.x + f0.y * w0.y + f1.x * w0.z + f1.y * w0.w;
        s += f2.x * w1.x + f2.y * w1.y + f3.x * w1.z + f3.y * w1.w;
    }
#pragma unroll
    for (int o = 16; o; o >>= 1) s += __shfl_xor_sync(0xffffffffu, s, o);
    if (lane == 0) out[n] = 1.f / (1.f + __expf(-(s + bend[0])));
}

// ---------------- host ----------------
extern "C" void kernel_launch(void* const* d_in, const int* in_sizes, int n_in,
                              void* d_out, int out_size) {
    const float* x    = (const float*)d_in[0];
    const void*  ei   = d_in[1];
    const float* ea   = (const float*)d_in[2];
    const float* We1  = (const float*)d_in[3];
    const float* be1  = (const float*)d_in[4];
    const float* W1   = (const float*)d_in[5];
    const float* b1   = (const float*)d_in[6];
    const float* We2  = (const float*)d_in[7];
    const float* be2  = (const float*)d_in[8];
    const float* W2   = (const float*)d_in[9];
    const float* b2   = (const float*)d_in[10];
    const float* Wend = (const float*)d_in[11];
    const float* bend = (const float*)d_in[12];
    float* out = (float*)d_out;

    // launch order matters for ncu (-s 5 profiles launch #5 = k_aggr)
    k_prep<<<256, 256>>>(ei, W2);                                     // 0
    k_hist<<<(N_EDGES + 255) / 256, 256>>>(ei);                       // 1
    k_scan1<<<SCAN_B, 256>>>();                                       // 2
    k_fillscat<<<(N_EDGES + 255) / 256, 256>>>(ei, ea, x, We1, be1);  // 3
    k_layer1nn<<<N_NODES, 256>>>(x, W1, b1);                          // 4

    // layer 2
    k_aggr<<<(N_NODES * 32 + 255) / 256, 256>>>(0, We2, be2);         // 5 (profiled)
    k_gemm_tc<<<dim3(2, (N_NODES + 127) / 128), 256>>>(2, b2);

    // layer 3
    k_aggr<<<(N_NODES * 32 + 255) / 256, 256>>>(1, We2, be2);
    k_gemm_tc<<<dim3(2, (N_NODES + 127) / 128), 256>>>(3, b2);

    k_final<<<(N_NODES + 7) / 8, 256>>>(Wend, bend, out);
}